// round 12
// baseline (speedup 1.0000x reference)
#include <cuda_runtime.h>
#include <math.h>
#include <stdint.h>

#define NB 2048

// ---------------- scratch (device globals; no allocation) ----------------
__device__ float g_h2[NB * 3600];           // conv2+pool out (tf32-rounded) [b][50][6][12]
__device__ float g_c [NB * 2];              // routed capsule outputs
__device__ float g_fp[4 * NB * 512];        // fc1 split-K partials [s][m][n(512)]
__device__ uint2 g_w2f[64 * 4 * 64];        // conv2 B frags: [kc][kk][n] tf32 pairs {k,k+4}
__device__ uint4 g_wpa[160 * 32];           // pcaps A frags (tf32, per-lane a0..a3)
__device__ uint2 g_w1p[452 * 4 * 512];      // fc1 B frags: [kc][kk][n] tf32 pairs {k,k+4}
__device__ int2  g_koffc[256];              // conv2 im2col offsets {k,k+4}
__device__ int2  g_koffp[640];              // pcaps im2col offsets {k,k+4}

// ---------------- helpers ----------------
__device__ __forceinline__ unsigned f2tf(float f) {
    unsigned u; asm("cvt.rna.tf32.f32 %0, %1;" : "=r"(u) : "f"(f)); return u;
}
__device__ __forceinline__ void mma8(float* d, unsigned a0, unsigned a1, unsigned a2,
                                     unsigned a3, unsigned b0, unsigned b1) {
    asm volatile(
        "mma.sync.aligned.m16n8k8.row.col.f32.tf32.tf32.f32 "
        "{%0,%1,%2,%3},{%4,%5,%6,%7},{%8,%9},{%0,%1,%2,%3};"
        : "+f"(d[0]), "+f"(d[1]), "+f"(d[2]), "+f"(d[3])
        : "r"(a0), "r"(a1), "r"(a2), "r"(a3), "r"(b0), "r"(b1));
}
__device__ __forceinline__ unsigned sptr(const void* p) {
    return (unsigned)__cvta_generic_to_shared(p);
}
#define CP_ASYNC8(dst, src)  asm volatile("cp.async.ca.shared.global [%0], [%1], 8;"  :: "r"(dst), "l"(src))
#define CP_ASYNC16(dst, src) asm volatile("cp.async.cg.shared.global [%0], [%1], 16;" :: "r"(dst), "l"(src))
#define CP_COMMIT            asm volatile("cp.async.commit_group;")
#define CP_WAIT(n)           asm volatile("cp.async.wait_group %0;" :: "n"(n))

// ---------------- prep: weight fragment layouts + im2col offset tables ----------------
__global__ void prep_k(const float* __restrict__ w2, const float* __restrict__ pw,
                       const float* __restrict__ w1) {
    int gtid = blockIdx.x * blockDim.x + threadIdx.x;
    int stride = gridDim.x * blockDim.x;
    for (int i = gtid; i < 16384; i += stride) {   // conv2 B frags
        int kc = i >> 8, rem = i & 255, kk = rem >> 6, n = rem & 63;
        int k = kc * 8 + kk;
        float v0 = (n < 50 && k     < 500) ? w2[n * 500 + k]     : 0.f;
        float v1 = (n < 50 && k + 4 < 500) ? w2[n * 500 + k + 4] : 0.f;
        g_w2f[i] = make_uint2(f2tf(v0), f2tf(v1));
    }
    for (int i = gtid; i < 5120; i += stride) {    // pcaps A frags
        int kc = i >> 5, lane = i & 31, g = lane >> 2, t = lane & 3;
        int k0 = kc * 8;
        float v0 = (k0 + t     < 1250) ? pw[g * 1250 + k0 + t]           : 0.f;
        float v1 = (k0 + t     < 1250) ? pw[(g + 8) * 1250 + k0 + t]     : 0.f;
        float v2 = (k0 + t + 4 < 1250) ? pw[g * 1250 + k0 + t + 4]       : 0.f;
        float v3 = (k0 + t + 4 < 1250) ? pw[(g + 8) * 1250 + k0 + t + 4] : 0.f;
        g_wpa[i] = make_uint4(f2tf(v0), f2tf(v1), f2tf(v2), f2tf(v3));
    }
    for (int i = gtid; i < 256; i += stride) {     // conv2 offsets
        int k = (i >> 2) * 8 + (i & 3);
        int o0 = (k < 500) ? (k / 25) * 448 + ((k % 25) / 5) * 28 + (k % 5) : 8960;
        int k4 = k + 4;
        int o1 = (k4 < 500) ? (k4 / 25) * 448 + ((k4 % 25) / 5) * 28 + (k4 % 5) : 8960;
        g_koffc[i] = make_int2(o0, o1);
    }
    for (int i = gtid; i < 640; i += stride) {     // pcaps offsets
        int k = (i >> 2) * 8 + (i & 3);
        int o0 = (k < 1250) ? (k / 25) * 160 + ((k % 25) / 5) * 16 + (k % 5) : 8000;
        int k4 = k + 4;
        int o1 = (k4 < 1250) ? (k4 / 25) * 160 + ((k4 % 25) / 5) * 16 + (k4 % 5) : 8000;
        g_koffp[i] = make_int2(o0, o1);
    }
    for (int i = gtid; i < 452 * 4 * 512; i += stride) {  // fc1 B frags (K padded to 3616)
        int kc = i >> 11, rem = i & 2047, kk = rem >> 9, n = rem & 511;
        int k = kc * 8 + kk;
        float v0 = (n < 500 && k     < 3602) ? w1[n * 3602 + k]     : 0.f;
        float v1 = (n < 500 && k + 4 < 3602) ? w1[n * 3602 + k + 4] : 0.f;
        g_w1p[i] = make_uint2(f2tf(v0), f2tf(v1));
    }
}

// ================= fused backbone =================
__device__ __forceinline__ float sq1(float s) { return s * fabsf(s) / (1.f + s * s); }

__global__ __launch_bounds__(288, 2) void backbone_k(
    const float* __restrict__ x, const float* __restrict__ c1w, const float* __restrict__ c1b,
    const float* __restrict__ c2b, const float* __restrict__ pcb, const float* __restrict__ rw) {
    extern __shared__ __align__(16) unsigned char cs[];
    unsigned* sxt    = (unsigned*)cs;
    uint2*    sBf0   = (uint2*)(cs + 37184);
    uint2*    sBf1   = (uint2*)(cs + 70464);
    float*    sconv  = (float*)cs;
    float*    sp     = (float*)cs;
    uint4*    swc    = (uint4*)(cs + 8192);
    float*    sx1    = (float*)(cs + 70464);
    unsigned* sh2p   = (unsigned*)(cs + 70464);
    int2*     skoffp = (int2*)(cs + 103744);
    __shared__ __align__(8) float sw1[640];   // conv1 weights: [oc][kr*6+kc], kr rows 6-padded
    __shared__ float sb1[20];
    __shared__ int2  skoffc[256];

    int b = blockIdx.x, tid = threadIdx.x;
    int warp = tid >> 5, lane = tid & 31, g = lane >> 2, t = lane & 3;

    for (int i = tid; i < 2160; i += 288) sx1[i] = x[b * 2160 + i];
    for (int i = tid; i < 640;  i += 288) {        // padded weight layout
        int oc = i >> 5, rem = i & 31;
        int r = rem / 6, c = rem % 6;
        sw1[i] = (rem < 30 && c < 5) ? c1w[oc * 25 + r * 5 + c] : 0.f;
    }
    if (tid < 20) sb1[tid] = c1b[tid];
    for (int i = tid; i < 256; i += 288) skoffc[i] = g_koffc[i];
    for (int i = tid; i < 640; i += 288) skoffp[i] = g_koffp[i];
    __syncthreads();

    for (int i = tid; i < 4096; i += 288) {
        int row = i >> 6, n = i & 63;
        CP_ASYNC8(sptr(&sBf0[row * 65 + n]), &g_w2f[i]);
    }
    CP_COMMIT;

    // ---- conv1 + pool (exact fp32): one patch per item serves 4 ocs; LDS.64 weights ----
    for (int i = tid; i < 2240; i += 288) {
        int og = i / 448, pos = i % 448;
        int ph = pos / 28, pw = pos % 28;
        int r0 = ph * 2, c0 = pw * 2;
        float patch[6][6];
#pragma unroll
        for (int pr = 0; pr < 6; pr++) {
            const float2* row = (const float2*)&sx1[(r0 + pr) * 60 + c0];
            float2 p0 = row[0], p1 = row[1], p2 = row[2];
            patch[pr][0] = p0.x; patch[pr][1] = p0.y;
            patch[pr][2] = p1.x; patch[pr][3] = p1.y;
            patch[pr][4] = p2.x; patch[pr][5] = p2.y;
        }
        int oc0 = og * 4;
#pragma unroll
        for (int o = 0; o < 4; o++) {
            const float* wp = &sw1[(oc0 + o) * 32];
            float a00 = 0, a01 = 0, a10 = 0, a11 = 0;
#pragma unroll
            for (int kr = 0; kr < 5; kr++) {
                float2 w01 = *(const float2*)&wp[kr * 6];
                float2 w23 = *(const float2*)&wp[kr * 6 + 2];
                float  w4  = wp[kr * 6 + 4];
                float wvs[5] = {w01.x, w01.y, w23.x, w23.y, w4};
#pragma unroll
                for (int kc = 0; kc < 5; kc++) {
                    float wv = wvs[kc];
                    a00 = fmaf(patch[kr][kc],         wv, a00);
                    a01 = fmaf(patch[kr][kc + 1],     wv, a01);
                    a10 = fmaf(patch[kr + 1][kc],     wv, a10);
                    a11 = fmaf(patch[kr + 1][kc + 1], wv, a11);
                }
            }
            sxt[(oc0 + o) * 448 + pos] =
                f2tf(fmaxf(fmaxf(a00, a01), fmaxf(a10, a11)) + sb1[oc0 + o]);
        }
    }
    for (int i = 8960 + tid; i < 9292; i += 288) sxt[i] = 0u;
    __syncthreads();

    for (int i = tid; i < 4096; i += 288) {
        int row = i >> 6, n = i & 63;
        CP_ASYNC8(sptr(&sBf1[row * 65 + n]), &g_w2f[4096 + i]);
    }
    CP_COMMIT;
    CP_WAIT(1);
    __syncthreads();

    float acc[2][7][4];
#pragma unroll
    for (int s = 0; s < 2; s++)
#pragma unroll
        for (int nt = 0; nt < 7; nt++)
#pragma unroll
            for (int q = 0; q < 4; q++) acc[s][nt][q] = 0.f;

    int pb[2][2];
#pragma unroll
    for (int s = 0; s < 2; s++) {
        int m0 = (warp * 2 + s) * 16 + g;
        pb[s][0] = (m0 / 24) * 28 + (m0 % 24);
        int m1 = m0 + 8;
        pb[s][1] = (m1 / 24) * 28 + (m1 % 24);
    }

    for (int win = 0; win < 4; win++) {
        uint2* sBf = (win & 1) ? sBf1 : sBf0;
#pragma unroll 4
        for (int wk = 0; wk < 16; wk++) {
            int2 ko = skoffc[(win * 16 + wk) * 4 + t];
            unsigned a[2][4];
#pragma unroll
            for (int s = 0; s < 2; s++) {
                a[s][0] = sxt[pb[s][0] + ko.x];
                a[s][1] = sxt[pb[s][1] + ko.x];
                a[s][2] = sxt[pb[s][0] + ko.y];
                a[s][3] = sxt[pb[s][1] + ko.y];
            }
#pragma unroll
            for (int nt = 0; nt < 7; nt++) {
                uint2 bb = sBf[(wk * 4 + t) * 65 + nt * 8 + g];
                mma8(acc[0][nt], a[0][0], a[0][1], a[0][2], a[0][3], bb.x, bb.y);
                mma8(acc[1][nt], a[1][0], a[1][1], a[1][2], a[1][3], bb.x, bb.y);
            }
        }
        __syncthreads();
        if (win < 2) {
            for (int i = tid; i < 4096; i += 288) {
                int row = i >> 6, n = i & 63;
                CP_ASYNC8(sptr(&sBf[row * 65 + n]), &g_w2f[(win + 2) * 4096 + i]);
            }
            CP_COMMIT;
            CP_WAIT(1);
        } else {
            CP_WAIT(0);
        }
        __syncthreads();
    }

#pragma unroll
    for (int s = 0; s < 2; s++) {
        int m0 = (warp * 2 + s) * 16 + g;
#pragma unroll
        for (int nt = 0; nt < 7; nt++) {
            int n0 = nt * 8 + 2 * t;
            if (n0 < 50) {
                sconv[n0 * 288 + m0]     = acc[s][nt][0];
                sconv[n0 * 288 + m0 + 8] = acc[s][nt][2];
            }
            if (n0 + 1 < 50) {
                sconv[(n0 + 1) * 288 + m0]     = acc[s][nt][1];
                sconv[(n0 + 1) * 288 + m0 + 8] = acc[s][nt][3];
            }
        }
    }
    for (int i = tid; i < 8096; i += 288) sh2p[i] = 0u;
    __syncthreads();

    for (int i = tid; i < 3600; i += 288) {
        int oc = i / 72, rem = i % 72, ph = rem / 12, pw = rem % 12;
        const float* base = &sconv[oc * 288 + ph * 48 + pw * 2];
        float m = fmaxf(fmaxf(base[0], base[1]), fmaxf(base[24], base[25])) + c2b[oc];
        unsigned r = f2tf(m);
        sh2p[oc * 160 + (ph + 2) * 16 + (pw + 2)] = r;
        g_h2[b * 3600 + i] = __uint_as_float(r);
    }
    __syncthreads();

    for (int i = tid; i < 1280; i += 288)
        CP_ASYNC16(sptr(&swc[i]), &g_wpa[i]);
    CP_COMMIT;
    for (int i = tid; i < 1280; i += 288)
        CP_ASYNC16(sptr(&swc[1280 + i]), &g_wpa[1280 + i]);
    CP_COMMIT;

    {
        int nt = warp;
        int p = nt * 8 + g;
        int pbase = (p / 12) * 16 + (p % 12);
        float pa4[4][4];
#pragma unroll
        for (int c = 0; c < 4; c++)
#pragma unroll
            for (int q = 0; q < 4; q++) pa4[c][q] = 0.f;

        for (int ch = 0; ch < 4; ch++) {
            if (ch < 3) { CP_WAIT(1); } else { CP_WAIT(0); }
            __syncthreads();
            const uint4* wbuf = &swc[(ch & 1) * 1280];
#pragma unroll 4
            for (int j = 0; j < 40; j++) {
                int kc = ch * 40 + j;
                uint4 aa = wbuf[j * 32 + lane];
                int2 ko = skoffp[kc * 4 + t];
                unsigned b0 = sh2p[ko.x + pbase];
                unsigned b1 = sh2p[ko.y + pbase];
                mma8(pa4[kc & 3], aa.x, aa.y, aa.z, aa.w, b0, b1);
            }
            __syncthreads();
            if (ch + 2 < 4) {
                for (int i = tid; i < 1280; i += 288)
                    CP_ASYNC16(sptr(&swc[(ch & 1) * 1280 + i]), &g_wpa[(ch + 2) * 1280 + i]);
                CP_COMMIT;
            }
        }
        float pa[4];
#pragma unroll
        for (int q = 0; q < 4; q++)
            pa[q] = (pa4[0][q] + pa4[1][q]) + (pa4[2][q] + pa4[3][q]);

        int oc0 = g;
        int n0 = nt * 8 + 2 * t;
        float bsA = pcb[oc0], bsB = pcb[oc0 + 8];
        sp[oc0 * 72 + n0]           = pa[0] + bsA;
        sp[oc0 * 72 + n0 + 1]       = pa[1] + bsA;
        sp[(oc0 + 8) * 72 + n0]     = pa[2] + bsB;
        sp[(oc0 + 8) * 72 + n0 + 1] = pa[3] + bsB;
    }
    __syncthreads();

    if (warp < 2) {
        int k = warp;
        float pr[9];
#pragma unroll
        for (int j = 0; j < 9; j++) {
            int r = lane + 32 * j;
            int cw = r / 72, hw = r % 72;
            const float* pbp = sp + cw * 72 + hw;
            float u0 = pbp[0], u1 = pbp[288], u2 = pbp[576], u3 = pbp[864];
            float n2 = u0 * u0 + u1 * u1 + u2 * u2 + u3 * u3;
            float f = sqrtf(n2) / (1.f + n2);
            float4 w4 = *(const float4*)&rw[(k * 288 + r) * 4];
            pr[j] = f * (u0 * w4.x + u1 * w4.y + u2 * w4.z + u3 * w4.w);
        }
        float S = 0.f;
#pragma unroll
        for (int j = 0; j < 9; j++) S += pr[j];
#pragma unroll
        for (int o = 16; o; o >>= 1) S += __shfl_xor_sync(0xffffffffu, S, o);
        float s = S * (1.f / 288.f);
        float v = sq1(s);
        float vsum = v;
#pragma unroll
        for (int it = 0; it < 2; it++) {
            float m = -1e30f;
#pragma unroll
            for (int j = 0; j < 9; j++) m = fmaxf(m, pr[j] * vsum);
#pragma unroll
            for (int o = 16; o; o >>= 1) m = fmaxf(m, __shfl_xor_sync(0xffffffffu, m, o));
            float Z = 0.f, T = 0.f;
#pragma unroll
            for (int j = 0; j < 9; j++) {
                float e = __expf(pr[j] * vsum - m);
                Z += e;
                T = fmaf(e, pr[j], T);
            }
#pragma unroll
            for (int o = 16; o; o >>= 1) {
                Z += __shfl_xor_sync(0xffffffffu, Z, o);
                T += __shfl_xor_sync(0xffffffffu, T, o);
            }
            float s2 = T / Z;
            v = sq1(s2);
            vsum += v;
        }
        if (lane == 0) g_c[b * 2 + k] = v;
    }
}

// ---------------- fc1 split-K: CTA tile 128m x 128n, Ksplit=4, 3-buf / 1 barrier/iter ----------------
// dyn smem: As[3][128*36] u32 (55296 B) | Bsp[3][16*132] uint2 (50688 B) = 105984 B
__global__ __launch_bounds__(256) void fc1_mma_k() {
    extern __shared__ __align__(16) unsigned char ds[];
    unsigned* As  = (unsigned*)ds;
    uint2*    Bsp = (uint2*)(ds + 55296);
    const int ASTRIDE = 128 * 36;
    const int BSTRIDE = 16 * 132;

    int n0 = blockIdx.x * 128, m0 = blockIdx.y * 128;
    int ks = blockIdx.z;
    int ktb = (113 * ks) >> 2;           // 0,28,56,84
    int kte = (113 * (ks + 1)) >> 2;     // 28,56,84,113
    int tid = threadIdx.x, warp = tid >> 5, lane = tid & 31, g = lane >> 2, t = lane & 3;
    int mA = tid & 127, kslA = (tid >> 7) * 16;
    int nB = tid & 127, kgB = tid >> 7;   // 0..1

    float acc[16][4];
#pragma unroll
    for (int nt = 0; nt < 16; nt++)
#pragma unroll
        for (int q = 0; q < 4; q++) acc[nt][q] = 0.f;

    auto stage = [&](int kt, int buf) {
        unsigned* A = &As[buf * ASTRIDE];
        if (kt < 112) {
            const float* src = &g_h2[(m0 + mA) * 3600 + kt * 32 + kslA];
            unsigned d0 = sptr(&A[mA * 36 + kslA]);
            CP_ASYNC16(d0,      src);
            CP_ASYNC16(d0 + 16, src + 4);
            CP_ASYNC16(d0 + 32, src + 8);
            CP_ASYNC16(d0 + 48, src + 12);
        } else {
#pragma unroll
            for (int q = 0; q < 16; q++) {
                int k = 3584 + kslA + q;
                unsigned v = 0u;
                if (k < 3600) v = __float_as_uint(g_h2[(m0 + mA) * 3600 + k]);
                else if (k < 3602) v = f2tf(g_c[(m0 + mA) * 2 + (k - 3600)]);
                A[mA * 36 + kslA + q] = v;
            }
        }
        uint2* B = &Bsp[buf * BSTRIDE];
#pragma unroll
        for (int r8 = 0; r8 < 8; r8++) {
            int row = kgB * 8 + r8;
            CP_ASYNC8(sptr(&B[row * 132 + nB]),
                      &g_w1p[(kt * 16 + row) * 512 + n0 + nB]);
        }
        CP_COMMIT;
    };

    stage(ktb,     0);
    stage(ktb + 1, 1);

    int buf = 0;
    for (int kt = ktb; kt < kte; kt++) {
        if (kt + 1 < kte) { CP_WAIT(1); } else { CP_WAIT(0); }
        __syncthreads();
        unsigned* A = &As[buf * ASTRIDE];
        uint2*    B = &Bsp[buf * BSTRIDE];
#pragma unroll
        for (int kc = 0; kc < 4; kc++) {
            int r0 = warp * 16 + g;
            unsigned a0 = A[r0 * 36 + kc * 8 + t];
            unsigned a1 = A[(r0 + 8) * 36 + kc * 8 + t];
            unsigned a2 = A[r0 * 36 + kc * 8 + t + 4];
            unsigned a3 = A[(r0 + 8) * 36 + kc * 8 + t + 4];
#pragma unroll
            for (int nt = 0; nt < 16; nt++) {
                uint2 bb = B[(kc * 4 + t) * 132 + nt * 8 + g];
                mma8(acc[nt], a0, a1, a2, a3, bb.x, bb.y);
            }
        }
        if (kt + 2 < kte) stage(kt + 2, (buf + 2) % 3);
        buf = (buf == 2) ? 0 : buf + 1;
    }

    float* dst = &g_fp[(size_t)ks * NB * 512];
    int mrow = m0 + warp * 16 + g;
#pragma unroll
    for (int nt = 0; nt < 16; nt++) {
        int n = n0 + nt * 8 + 2 * t;
        dst[mrow * 512 + n]           = acc[nt][0];
        dst[mrow * 512 + n + 1]       = acc[nt][1];
        dst[(mrow + 8) * 512 + n]     = acc[nt][2];
        dst[(mrow + 8) * 512 + n + 1] = acc[nt][3];
    }
}

// ---------------- fused fc1-reduce + fc2: one warp per image, float4 partial loads ----------------
__global__ __launch_bounds__(256) void fc2_k(
    const float* __restrict__ y, const float* __restrict__ f1b,
    const float* __restrict__ w2, const float* __restrict__ b2, float* __restrict__ out) {
    const int S = NB * 512;
    int b = (blockIdx.x * blockDim.x + threadIdx.x) >> 5;
    int lane = threadIdx.x & 31;
    const float* w0 = w2;
    const float* w1 = w2 + 502;
    float a0 = 0.f, a1 = 0.f;
    for (int i4 = lane; i4 < 125; i4 += 32) {
        int j = i4 * 4, o = b * 512 + j;
        float4 p0 = *(const float4*)&g_fp[o];
        float4 p1 = *(const float4*)&g_fp[S + o];
        float4 p2 = *(const float4*)&g_fp[2 * S + o];
        float4 p3 = *(const float4*)&g_fp[3 * S + o];
        float4 bi = *(const float4*)&f1b[j];
        float4 wv = *(const float4*)&w0[j];
        float v0 = fmaxf((p0.x + p1.x) + (p2.x + p3.x) + bi.x, 0.f);
        float v1 = fmaxf((p0.y + p1.y) + (p2.y + p3.y) + bi.y, 0.f);
        float v2 = fmaxf((p0.z + p1.z) + (p2.z + p3.z) + bi.z, 0.f);
        float v3 = fmaxf((p0.w + p1.w) + (p2.w + p3.w) + bi.w, 0.f);
        a0 = fmaf(v0, wv.x, a0); a0 = fmaf(v1, wv.y, a0);
        a0 = fmaf(v2, wv.z, a0); a0 = fmaf(v3, wv.w, a0);
        a1 = fmaf(v0, w1[j],     a1); a1 = fmaf(v1, w1[j + 1], a1);
        a1 = fmaf(v2, w1[j + 2], a1); a1 = fmaf(v3, w1[j + 3], a1);
    }
    if (lane == 0) {
        float y0 = y[b * 2], y1 = y[b * 2 + 1];
        a0 += w0[500] * y0 + w0[501] * y1 + b2[0];
        a1 += w1[500] * y0 + w1[501] * y1 + b2[1];
    }
#pragma unroll
    for (int off = 16; off; off >>= 1) {
        a0 += __shfl_xor_sync(0xffffffffu, a0, off);
        a1 += __shfl_xor_sync(0xffffffffu, a1, off);
    }
    if (lane == 0) {
        out[b * 2]     = a0;
        out[b * 2 + 1] = a1;
    }
}

// ---------------- launch ----------------
extern "C" void kernel_launch(void* const* d_in, const int* in_sizes, int n_in,
                              void* d_out, int out_size) {
    const float* x   = (const float*)d_in[0];
    const float* y   = (const float*)d_in[1];
    const float* c1w = (const float*)d_in[2];
    const float* c1b = (const float*)d_in[3];
    const float* c2w = (const float*)d_in[4];
    const float* c2b = (const float*)d_in[5];
    const float* pw  = (const float*)d_in[6];
    const float* pb  = (const float*)d_in[7];
    const float* rw  = (const float*)d_in[8];
    const float* f1w = (const float*)d_in[9];
    const float* f1b = (const float*)d_in[10];
    const float* f2w = (const float*)d_in[11];
    const float* f2b = (const float*)d_in[12];
    float* out = (float*)d_out;

    const int bb_smem  = 108864;
    const int fc1_smem = 105984;
    cudaFuncSetAttribute(backbone_k, cudaFuncAttributeMaxDynamicSharedMemorySize, bb_smem);
    cudaFuncSetAttribute(fc1_mma_k,  cudaFuncAttributeMaxDynamicSharedMemorySize, fc1_smem);

    prep_k<<<512, 256>>>(c2w, pw, f1w);
    backbone_k<<<NB, 288, bb_smem>>>(x, c1w, c1b, c2b, pb, rw);
    dim3 g4(4, 16, 4);
    fc1_mma_k<<<g4, 256, fc1_smem>>>();
    fc2_k<<<NB / 8, 256>>>(y, f1b, f2w, f2b, out);
}

// round 13
// speedup vs baseline: 1.0550x; 1.0550x over previous
#include <cuda_runtime.h>
#include <cuda_fp16.h>
#include <math.h>
#include <stdint.h>

#define NB 2048

// ---------------- scratch (device globals; no allocation) ----------------
__device__ __half g_h2h[NB * 3600];         // conv2+pool out (fp16, == tf32 grid) [b][3600]
__device__ float g_c [NB * 2];              // routed capsule outputs
__device__ float g_fp[4 * NB * 512];        // fc1 split-K partials [s][m][n(512)]
__device__ uint2 g_w2f[64 * 4 * 64];        // conv2 B frags: [kc][kk][n] tf32 pairs {k,k+4}
__device__ uint4 g_wpa[160 * 32];           // pcaps A frags (tf32, per-lane a0..a3)
__device__ unsigned g_w1h[226 * 8 * 512];   // fc1 B frags fp16: [kc16][p][n] half2 {2p,2p+1}
__device__ int2  g_koffc[256];              // conv2 im2col offsets {k,k+4}
__device__ int2  g_koffp[640];              // pcaps im2col offsets {k,k+4}

// ---------------- helpers ----------------
__device__ __forceinline__ unsigned f2tf(float f) {
    unsigned u; asm("cvt.rna.tf32.f32 %0, %1;" : "=r"(u) : "f"(f)); return u;
}
__device__ __forceinline__ void mma8(float* d, unsigned a0, unsigned a1, unsigned a2,
                                     unsigned a3, unsigned b0, unsigned b1) {
    asm volatile(
        "mma.sync.aligned.m16n8k8.row.col.f32.tf32.tf32.f32 "
        "{%0,%1,%2,%3},{%4,%5,%6,%7},{%8,%9},{%0,%1,%2,%3};"
        : "+f"(d[0]), "+f"(d[1]), "+f"(d[2]), "+f"(d[3])
        : "r"(a0), "r"(a1), "r"(a2), "r"(a3), "r"(b0), "r"(b1));
}
__device__ __forceinline__ void mma16h(float* d, unsigned a0, unsigned a1, unsigned a2,
                                       unsigned a3, unsigned b0, unsigned b1) {
    asm volatile(
        "mma.sync.aligned.m16n8k16.row.col.f32.f16.f16.f32 "
        "{%0,%1,%2,%3},{%4,%5,%6,%7},{%8,%9},{%0,%1,%2,%3};"
        : "+f"(d[0]), "+f"(d[1]), "+f"(d[2]), "+f"(d[3])
        : "r"(a0), "r"(a1), "r"(a2), "r"(a3), "r"(b0), "r"(b1));
}
__device__ __forceinline__ unsigned packh2(float a, float b) {
    __half2 h = __floats2half2_rn(a, b);
    return *(unsigned*)&h;
}
__device__ __forceinline__ unsigned sptr(const void* p) {
    return (unsigned)__cvta_generic_to_shared(p);
}
#define CP_ASYNC8(dst, src)  asm volatile("cp.async.ca.shared.global [%0], [%1], 8;"  :: "r"(dst), "l"(src))
#define CP_ASYNC16(dst, src) asm volatile("cp.async.cg.shared.global [%0], [%1], 16;" :: "r"(dst), "l"(src))
#define CP_COMMIT            asm volatile("cp.async.commit_group;")
#define CP_WAIT(n)           asm volatile("cp.async.wait_group %0;" :: "n"(n))

// ---------------- prep: weight fragment layouts + im2col offset tables ----------------
__global__ void prep_k(const float* __restrict__ w2, const float* __restrict__ pw,
                       const float* __restrict__ w1) {
    int gtid = blockIdx.x * blockDim.x + threadIdx.x;
    int stride = gridDim.x * blockDim.x;
    for (int i = gtid; i < 16384; i += stride) {   // conv2 B frags
        int kc = i >> 8, rem = i & 255, kk = rem >> 6, n = rem & 63;
        int k = kc * 8 + kk;
        float v0 = (n < 50 && k     < 500) ? w2[n * 500 + k]     : 0.f;
        float v1 = (n < 50 && k + 4 < 500) ? w2[n * 500 + k + 4] : 0.f;
        g_w2f[i] = make_uint2(f2tf(v0), f2tf(v1));
    }
    for (int i = gtid; i < 5120; i += stride) {    // pcaps A frags
        int kc = i >> 5, lane = i & 31, g = lane >> 2, t = lane & 3;
        int k0 = kc * 8;
        float v0 = (k0 + t     < 1250) ? pw[g * 1250 + k0 + t]           : 0.f;
        float v1 = (k0 + t     < 1250) ? pw[(g + 8) * 1250 + k0 + t]     : 0.f;
        float v2 = (k0 + t + 4 < 1250) ? pw[g * 1250 + k0 + t + 4]       : 0.f;
        float v3 = (k0 + t + 4 < 1250) ? pw[(g + 8) * 1250 + k0 + t + 4] : 0.f;
        g_wpa[i] = make_uint4(f2tf(v0), f2tf(v1), f2tf(v2), f2tf(v3));
    }
    for (int i = gtid; i < 256; i += stride) {     // conv2 offsets
        int k = (i >> 2) * 8 + (i & 3);
        int o0 = (k < 500) ? (k / 25) * 448 + ((k % 25) / 5) * 28 + (k % 5) : 8960;
        int k4 = k + 4;
        int o1 = (k4 < 500) ? (k4 / 25) * 448 + ((k4 % 25) / 5) * 28 + (k4 % 5) : 8960;
        g_koffc[i] = make_int2(o0, o1);
    }
    for (int i = gtid; i < 640; i += stride) {     // pcaps offsets
        int k = (i >> 2) * 8 + (i & 3);
        int o0 = (k < 1250) ? (k / 25) * 160 + ((k % 25) / 5) * 16 + (k % 5) : 8000;
        int k4 = k + 4;
        int o1 = (k4 < 1250) ? (k4 / 25) * 160 + ((k4 % 25) / 5) * 16 + (k4 % 5) : 8000;
        g_koffp[i] = make_int2(o0, o1);
    }
    for (int i = gtid; i < 226 * 8 * 512; i += stride) {  // fc1 B frags fp16 (K pad 3616)
        int kc = i >> 12, rem = i & 4095, p = rem >> 9, n = rem & 511;
        int k = kc * 16 + 2 * p;
        float v0 = (n < 500 && k     < 3602) ? w1[n * 3602 + k]     : 0.f;
        float v1 = (n < 500 && k + 1 < 3602) ? w1[n * 3602 + k + 1] : 0.f;
        g_w1h[i] = packh2(v0, v1);
    }
}

// ================= fused backbone =================
__device__ __forceinline__ float sq1(float s) { return s * fabsf(s) / (1.f + s * s); }

__global__ __launch_bounds__(288, 2) void backbone_k(
    const float* __restrict__ x, const float* __restrict__ c1w, const float* __restrict__ c1b,
    const float* __restrict__ c2b, const float* __restrict__ pcb, const float* __restrict__ rw) {
    extern __shared__ __align__(16) unsigned char cs[];
    unsigned* sxt    = (unsigned*)cs;
    uint2*    sBf0   = (uint2*)(cs + 37184);
    uint2*    sBf1   = (uint2*)(cs + 70464);
    float*    sconv  = (float*)cs;
    float*    sp     = (float*)cs;
    uint4*    swc    = (uint4*)(cs + 8192);
    float*    sx1    = (float*)(cs + 70464);
    unsigned* sh2p   = (unsigned*)(cs + 70464);
    int2*     skoffp = (int2*)(cs + 103744);
    __shared__ __align__(8) float sw1[640];   // conv1 weights: [oc][kr*6+kc], kr rows 6-padded
    __shared__ float sb1[20];
    __shared__ int2  skoffc[256];

    int b = blockIdx.x, tid = threadIdx.x;
    int warp = tid >> 5, lane = tid & 31, g = lane >> 2, t = lane & 3;

    for (int i = tid; i < 2160; i += 288) sx1[i] = x[b * 2160 + i];
    for (int i = tid; i < 640;  i += 288) {
        int oc = i >> 5, rem = i & 31;
        int r = rem / 6, c = rem % 6;
        sw1[i] = (rem < 30 && c < 5) ? c1w[oc * 25 + r * 5 + c] : 0.f;
    }
    if (tid < 20) sb1[tid] = c1b[tid];
    for (int i = tid; i < 256; i += 288) skoffc[i] = g_koffc[i];
    for (int i = tid; i < 640; i += 288) skoffp[i] = g_koffp[i];
    __syncthreads();

    for (int i = tid; i < 4096; i += 288) {
        int row = i >> 6, n = i & 63;
        CP_ASYNC8(sptr(&sBf0[row * 65 + n]), &g_w2f[i]);
    }
    CP_COMMIT;

    // ---- conv1 + pool (exact fp32) ----
    for (int i = tid; i < 2240; i += 288) {
        int og = i / 448, pos = i % 448;
        int ph = pos / 28, pw = pos % 28;
        int r0 = ph * 2, c0 = pw * 2;
        float patch[6][6];
#pragma unroll
        for (int pr = 0; pr < 6; pr++) {
            const float2* row = (const float2*)&sx1[(r0 + pr) * 60 + c0];
            float2 p0 = row[0], p1 = row[1], p2 = row[2];
            patch[pr][0] = p0.x; patch[pr][1] = p0.y;
            patch[pr][2] = p1.x; patch[pr][3] = p1.y;
            patch[pr][4] = p2.x; patch[pr][5] = p2.y;
        }
        int oc0 = og * 4;
#pragma unroll
        for (int o = 0; o < 4; o++) {
            const float* wp = &sw1[(oc0 + o) * 32];
            float a00 = 0, a01 = 0, a10 = 0, a11 = 0;
#pragma unroll
            for (int kr = 0; kr < 5; kr++) {
                float2 w01 = *(const float2*)&wp[kr * 6];
                float2 w23 = *(const float2*)&wp[kr * 6 + 2];
                float  w4  = wp[kr * 6 + 4];
                float wvs[5] = {w01.x, w01.y, w23.x, w23.y, w4};
#pragma unroll
                for (int kc = 0; kc < 5; kc++) {
                    float wv = wvs[kc];
                    a00 = fmaf(patch[kr][kc],         wv, a00);
                    a01 = fmaf(patch[kr][kc + 1],     wv, a01);
                    a10 = fmaf(patch[kr + 1][kc],     wv, a10);
                    a11 = fmaf(patch[kr + 1][kc + 1], wv, a11);
                }
            }
            sxt[(oc0 + o) * 448 + pos] =
                f2tf(fmaxf(fmaxf(a00, a01), fmaxf(a10, a11)) + sb1[oc0 + o]);
        }
    }
    for (int i = 8960 + tid; i < 9292; i += 288) sxt[i] = 0u;
    __syncthreads();

    for (int i = tid; i < 4096; i += 288) {
        int row = i >> 6, n = i & 63;
        CP_ASYNC8(sptr(&sBf1[row * 65 + n]), &g_w2f[4096 + i]);
    }
    CP_COMMIT;
    CP_WAIT(1);
    __syncthreads();

    // ---- conv2 via tf32 mma ----
    float acc[2][7][4];
#pragma unroll
    for (int s = 0; s < 2; s++)
#pragma unroll
        for (int nt = 0; nt < 7; nt++)
#pragma unroll
            for (int q = 0; q < 4; q++) acc[s][nt][q] = 0.f;

    int pb[2][2];
#pragma unroll
    for (int s = 0; s < 2; s++) {
        int m0 = (warp * 2 + s) * 16 + g;
        pb[s][0] = (m0 / 24) * 28 + (m0 % 24);
        int m1 = m0 + 8;
        pb[s][1] = (m1 / 24) * 28 + (m1 % 24);
    }

    for (int win = 0; win < 4; win++) {
        uint2* sBf = (win & 1) ? sBf1 : sBf0;
#pragma unroll 4
        for (int wk = 0; wk < 16; wk++) {
            int2 ko = skoffc[(win * 16 + wk) * 4 + t];
            unsigned a[2][4];
#pragma unroll
            for (int s = 0; s < 2; s++) {
                a[s][0] = sxt[pb[s][0] + ko.x];
                a[s][1] = sxt[pb[s][1] + ko.x];
                a[s][2] = sxt[pb[s][0] + ko.y];
                a[s][3] = sxt[pb[s][1] + ko.y];
            }
#pragma unroll
            for (int nt = 0; nt < 7; nt++) {
                uint2 bb = sBf[(wk * 4 + t) * 65 + nt * 8 + g];
                mma8(acc[0][nt], a[0][0], a[0][1], a[0][2], a[0][3], bb.x, bb.y);
                mma8(acc[1][nt], a[1][0], a[1][1], a[1][2], a[1][3], bb.x, bb.y);
            }
        }
        __syncthreads();
        if (win < 2) {
            for (int i = tid; i < 4096; i += 288) {
                int row = i >> 6, n = i & 63;
                CP_ASYNC8(sptr(&sBf[row * 65 + n]), &g_w2f[(win + 2) * 4096 + i]);
            }
            CP_COMMIT;
            CP_WAIT(1);
        } else {
            CP_WAIT(0);
        }
        __syncthreads();
    }

#pragma unroll
    for (int s = 0; s < 2; s++) {
        int m0 = (warp * 2 + s) * 16 + g;
#pragma unroll
        for (int nt = 0; nt < 7; nt++) {
            int n0 = nt * 8 + 2 * t;
            if (n0 < 50) {
                sconv[n0 * 288 + m0]     = acc[s][nt][0];
                sconv[n0 * 288 + m0 + 8] = acc[s][nt][2];
            }
            if (n0 + 1 < 50) {
                sconv[(n0 + 1) * 288 + m0]     = acc[s][nt][1];
                sconv[(n0 + 1) * 288 + m0 + 8] = acc[s][nt][3];
            }
        }
    }
    for (int i = tid; i < 8096; i += 288) sh2p[i] = 0u;
    __syncthreads();

    // ---- maxpool + bias -> tf32 smem (pcaps) + fp16 gmem (fc1; same rounding grid) ----
    for (int i = tid; i < 3600; i += 288) {
        int oc = i / 72, rem = i % 72, ph = rem / 12, pw = rem % 12;
        const float* base = &sconv[oc * 288 + ph * 48 + pw * 2];
        float m = fmaxf(fmaxf(base[0], base[1]), fmaxf(base[24], base[25])) + c2b[oc];
        sh2p[oc * 160 + (ph + 2) * 16 + (pw + 2)] = f2tf(m);
        g_h2h[b * 3600 + i] = __float2half_rn(m);
    }
    __syncthreads();

    for (int i = tid; i < 1280; i += 288)
        CP_ASYNC16(sptr(&swc[i]), &g_wpa[i]);
    CP_COMMIT;
    for (int i = tid; i < 1280; i += 288)
        CP_ASYNC16(sptr(&swc[1280 + i]), &g_wpa[1280 + i]);
    CP_COMMIT;

    // ---- pcaps via tf32 mma ----
    {
        int nt = warp;
        int p = nt * 8 + g;
        int pbase = (p / 12) * 16 + (p % 12);
        float pa4[4][4];
#pragma unroll
        for (int c = 0; c < 4; c++)
#pragma unroll
            for (int q = 0; q < 4; q++) pa4[c][q] = 0.f;

        for (int ch = 0; ch < 4; ch++) {
            if (ch < 3) { CP_WAIT(1); } else { CP_WAIT(0); }
            __syncthreads();
            const uint4* wbuf = &swc[(ch & 1) * 1280];
#pragma unroll 4
            for (int j = 0; j < 40; j++) {
                int kc = ch * 40 + j;
                uint4 aa = wbuf[j * 32 + lane];
                int2 ko = skoffp[kc * 4 + t];
                unsigned b0 = sh2p[ko.x + pbase];
                unsigned b1 = sh2p[ko.y + pbase];
                mma8(pa4[kc & 3], aa.x, aa.y, aa.z, aa.w, b0, b1);
            }
            __syncthreads();
            if (ch + 2 < 4) {
                for (int i = tid; i < 1280; i += 288)
                    CP_ASYNC16(sptr(&swc[(ch & 1) * 1280 + i]), &g_wpa[(ch + 2) * 1280 + i]);
                CP_COMMIT;
            }
        }
        float pa[4];
#pragma unroll
        for (int q = 0; q < 4; q++)
            pa[q] = (pa4[0][q] + pa4[1][q]) + (pa4[2][q] + pa4[3][q]);

        int oc0 = g;
        int n0 = nt * 8 + 2 * t;
        float bsA = pcb[oc0], bsB = pcb[oc0 + 8];
        sp[oc0 * 72 + n0]           = pa[0] + bsA;
        sp[oc0 * 72 + n0 + 1]       = pa[1] + bsA;
        sp[(oc0 + 8) * 72 + n0]     = pa[2] + bsB;
        sp[(oc0 + 8) * 72 + n0 + 1] = pa[3] + bsB;
    }
    __syncthreads();

    // ---- squash + priors + 3-iter routing ----
    if (warp < 2) {
        int k = warp;
        float pr[9];
#pragma unroll
        for (int j = 0; j < 9; j++) {
            int r = lane + 32 * j;
            int cw = r / 72, hw = r % 72;
            const float* pbp = sp + cw * 72 + hw;
            float u0 = pbp[0], u1 = pbp[288], u2 = pbp[576], u3 = pbp[864];
            float n2 = u0 * u0 + u1 * u1 + u2 * u2 + u3 * u3;
            float f = sqrtf(n2) / (1.f + n2);
            float4 w4 = *(const float4*)&rw[(k * 288 + r) * 4];
            pr[j] = f * (u0 * w4.x + u1 * w4.y + u2 * w4.z + u3 * w4.w);
        }
        float S = 0.f;
#pragma unroll
        for (int j = 0; j < 9; j++) S += pr[j];
#pragma unroll
        for (int o = 16; o; o >>= 1) S += __shfl_xor_sync(0xffffffffu, S, o);
        float s = S * (1.f / 288.f);
        float v = sq1(s);
        float vsum = v;
#pragma unroll
        for (int it = 0; it < 2; it++) {
            float m = -1e30f;
#pragma unroll
            for (int j = 0; j < 9; j++) m = fmaxf(m, pr[j] * vsum);
#pragma unroll
            for (int o = 16; o; o >>= 1) m = fmaxf(m, __shfl_xor_sync(0xffffffffu, m, o));
            float Z = 0.f, T = 0.f;
#pragma unroll
            for (int j = 0; j < 9; j++) {
                float e = __expf(pr[j] * vsum - m);
                Z += e;
                T = fmaf(e, pr[j], T);
            }
#pragma unroll
            for (int o = 16; o; o >>= 1) {
                Z += __shfl_xor_sync(0xffffffffu, Z, o);
                T += __shfl_xor_sync(0xffffffffu, T, o);
            }
            float s2 = T / Z;
            v = sq1(s2);
            vsum += v;
        }
        if (lane == 0) g_c[b * 2 + k] = v;
    }
}

// ---------------- fc1 split-K fp16: CTA tile 128m x 128n, Ksplit=4, m16n8k16 ----------------
// dyn smem: As[3][128*40 halves] (30720 B) | Bh[3][16*132] uint (25344 B) = 56064 B
__global__ __launch_bounds__(256) void fc1_mma_k() {
    extern __shared__ __align__(16) unsigned char ds[];
    __half*   As = (__half*)ds;
    unsigned* Bh = (unsigned*)(ds + 30720);
    const int ASTR = 128 * 40;     // halves per buffer
    const int BSTR = 16 * 132;     // uints per buffer

    int n0 = blockIdx.x * 128, m0 = blockIdx.y * 128;
    int ks = blockIdx.z;
    int ktb = (113 * ks) >> 2;           // 0,28,56,84
    int kte = (113 * (ks + 1)) >> 2;     // 28,56,84,113
    int tid = threadIdx.x, warp = tid >> 5, lane = tid & 31, g = lane >> 2, t = lane & 3;

    float acc[16][4];
#pragma unroll
    for (int nt = 0; nt < 16; nt++)
#pragma unroll
        for (int q = 0; q < 4; q++) acc[nt][q] = 0.f;

    auto stage = [&](int kt, int buf) {
        __half* A = &As[buf * ASTR];
        int rowA = tid >> 1, halfA = tid & 1;
        if (kt < 112) {
            const __half* src = &g_h2h[(m0 + rowA) * 3600 + kt * 32 + halfA * 16];
            unsigned d0 = sptr(&A[rowA * 40 + halfA * 16]);
            CP_ASYNC16(d0, src);
            CP_ASYNC16(d0 + 16, src + 8);
        } else {
            if (halfA == 0) {
#pragma unroll
                for (int q = 0; q < 16; q++)
                    A[rowA * 40 + q] = g_h2h[(m0 + rowA) * 3600 + 3584 + q];
            } else {
#pragma unroll
                for (int q = 0; q < 16; q++) {
                    int k = 3600 + q;
                    __half v = __float2half_rn(0.f);
                    if (k < 3602) v = __float2half_rn(g_c[(m0 + rowA) * 2 + (k - 3600)]);
                    A[rowA * 40 + 16 + q] = v;
                }
            }
        }
        unsigned* B = &Bh[buf * BSTR];
        int rowB = tid >> 4, offB = (tid & 15) * 8;
        unsigned dB = sptr(&B[rowB * 132 + offB]);
        const unsigned* sB = &g_w1h[(kt * 16 + rowB) * 512 + n0 + offB];
        CP_ASYNC16(dB, sB);
        CP_ASYNC16(dB + 16, sB + 4);
        CP_COMMIT;
    };

    stage(ktb,     0);
    stage(ktb + 1, 1);

    int buf = 0;
    for (int kt = ktb; kt < kte; kt++) {
        if (kt + 1 < kte) { CP_WAIT(1); } else { CP_WAIT(0); }
        __syncthreads();
        const unsigned* Au = (const unsigned*)&As[buf * ASTR];
        const unsigned* B  = &Bh[buf * BSTR];
        int r0 = warp * 16 + g;
#pragma unroll
        for (int c = 0; c < 2; c++) {
            unsigned a0 = Au[r0 * 20 + c * 8 + t];
            unsigned a1 = Au[(r0 + 8) * 20 + c * 8 + t];
            unsigned a2 = Au[r0 * 20 + c * 8 + t + 4];
            unsigned a3 = Au[(r0 + 8) * 20 + c * 8 + t + 4];
#pragma unroll
            for (int nt = 0; nt < 16; nt++) {
                unsigned b0 = B[(c * 8 + t) * 132 + nt * 8 + g];
                unsigned b1 = B[(c * 8 + t + 4) * 132 + nt * 8 + g];
                mma16h(acc[nt], a0, a1, a2, a3, b0, b1);
            }
        }
        if (kt + 2 < kte) stage(kt + 2, (buf + 2) % 3);
        buf = (buf == 2) ? 0 : buf + 1;
    }

    float* dst = &g_fp[(size_t)ks * NB * 512];
    int mrow = m0 + warp * 16 + g;
#pragma unroll
    for (int nt = 0; nt < 16; nt++) {
        int n = n0 + nt * 8 + 2 * t;
        dst[mrow * 512 + n]           = acc[nt][0];
        dst[mrow * 512 + n + 1]       = acc[nt][1];
        dst[(mrow + 8) * 512 + n]     = acc[nt][2];
        dst[(mrow + 8) * 512 + n + 1] = acc[nt][3];
    }
}

// ---------------- fused fc1-reduce + fc2: one warp per image, float4 partial loads ----------------
__global__ __launch_bounds__(256) void fc2_k(
    const float* __restrict__ y, const float* __restrict__ f1b,
    const float* __restrict__ w2, const float* __restrict__ b2, float* __restrict__ out) {
    const int S = NB * 512;
    int b = (blockIdx.x * blockDim.x + threadIdx.x) >> 5;
    int lane = threadIdx.x & 31;
    const float* w0 = w2;
    const float* w1 = w2 + 502;
    float a0 = 0.f, a1 = 0.f;
    for (int i4 = lane; i4 < 125; i4 += 32) {
        int j = i4 * 4, o = b * 512 + j;
        float4 p0 = *(const float4*)&g_fp[o];
        float4 p1 = *(const float4*)&g_fp[S + o];
        float4 p2 = *(const float4*)&g_fp[2 * S + o];
        float4 p3 = *(const float4*)&g_fp[3 * S + o];
        float4 bi = *(const float4*)&f1b[j];
        float4 wv = *(const float4*)&w0[j];
        float v0 = fmaxf((p0.x + p1.x) + (p2.x + p3.x) + bi.x, 0.f);
        float v1 = fmaxf((p0.y + p1.y) + (p2.y + p3.y) + bi.y, 0.f);
        float v2 = fmaxf((p0.z + p1.z) + (p2.z + p3.z) + bi.z, 0.f);
        float v3 = fmaxf((p0.w + p1.w) + (p2.w + p3.w) + bi.w, 0.f);
        a0 = fmaf(v0, wv.x, a0); a0 = fmaf(v1, wv.y, a0);
        a0 = fmaf(v2, wv.z, a0); a0 = fmaf(v3, wv.w, a0);
        a1 = fmaf(v0, w1[j],     a1); a1 = fmaf(v1, w1[j + 1], a1);
        a1 = fmaf(v2, w1[j + 2], a1); a1 = fmaf(v3, w1[j + 3], a1);
    }
    if (lane == 0) {
        float y0 = y[b * 2], y1 = y[b * 2 + 1];
        a0 += w0[500] * y0 + w0[501] * y1 + b2[0];
        a1 += w1[500] * y0 + w1[501] * y1 + b2[1];
    }
#pragma unroll
    for (int off = 16; off; off >>= 1) {
        a0 += __shfl_xor_sync(0xffffffffu, a0, off);
        a1 += __shfl_xor_sync(0xffffffffu, a1, off);
    }
    if (lane == 0) {
        out[b * 2]     = a0;
        out[b * 2 + 1] = a1;
    }
}

// ---------------- launch ----------------
extern "C" void kernel_launch(void* const* d_in, const int* in_sizes, int n_in,
                              void* d_out, int out_size) {
    const float* x   = (const float*)d_in[0];
    const float* y   = (const float*)d_in[1];
    const float* c1w = (const float*)d_in[2];
    const float* c1b = (const float*)d_in[3];
    const float* c2w = (const float*)d_in[4];
    const float* c2b = (const float*)d_in[5];
    const float* pw  = (const float*)d_in[6];
    const float* pb  = (const float*)d_in[7];
    const float* rw  = (const float*)d_in[8];
    const float* f1w = (const float*)d_in[9];
    const float* f1b = (const float*)d_in[10];
    const float* f2w = (const float*)d_in[11];
    const float* f2b = (const float*)d_in[12];
    float* out = (float*)d_out;

    const int bb_smem  = 108864;
    const int fc1_smem = 56064;
    cudaFuncSetAttribute(backbone_k, cudaFuncAttributeMaxDynamicSharedMemorySize, bb_smem);
    cudaFuncSetAttribute(fc1_mma_k,  cudaFuncAttributeMaxDynamicSharedMemorySize, fc1_smem);

    prep_k<<<512, 256>>>(c2w, pw, f1w);
    backbone_k<<<NB, 288, bb_smem>>>(x, c1w, c1b, c2b, pb, rw);
    dim3 g4(4, 16, 4);
    fc1_mma_k<<<g4, 256, fc1_smem>>>();
    fc2_k<<<NB / 8, 256>>>(y, f1b, f2w, f2b, out);
}

// round 14
// speedup vs baseline: 1.4930x; 1.4152x over previous
#include <cuda_runtime.h>
#include <cuda_fp16.h>
#include <math.h>
#include <stdint.h>

#define NB 2048

// ---------------- scratch (device globals; no allocation) ----------------
__device__ __half g_h2h[NB * 3600];         // conv2+pool out (fp16 == tf32 grid) [b][3600]
__device__ float g_c [NB * 2];              // routed capsule outputs
__device__ float g_fp[4 * NB * 512];        // fc1 split-K partials [s][m][n(512)]
__device__ unsigned g_w2fh[38 * 8 * 56];    // conv2 B frags fp16: [chunk][pair][n] half2
__device__ uint4 g_wpa[160 * 32];           // pcaps A frags (tf32, per-lane a0..a3)
__device__ unsigned g_w1h[226 * 8 * 512];   // fc1 B frags fp16: [kc16][p][n] half2
__device__ int2  g_koffc2[304];             // conv2 pair offsets {lo,hi} (zero slot 9216)
__device__ int2  g_koffp[640];              // pcaps im2col offsets {k,k+4}

// ---------------- helpers ----------------
__device__ __forceinline__ unsigned f2tf(float f) {
    unsigned u; asm("cvt.rna.tf32.f32 %0, %1;" : "=r"(u) : "f"(f)); return u;
}
__device__ __forceinline__ void mma8(float* d, unsigned a0, unsigned a1, unsigned a2,
                                     unsigned a3, unsigned b0, unsigned b1) {
    asm volatile(
        "mma.sync.aligned.m16n8k8.row.col.f32.tf32.tf32.f32 "
        "{%0,%1,%2,%3},{%4,%5,%6,%7},{%8,%9},{%0,%1,%2,%3};"
        : "+f"(d[0]), "+f"(d[1]), "+f"(d[2]), "+f"(d[3])
        : "r"(a0), "r"(a1), "r"(a2), "r"(a3), "r"(b0), "r"(b1));
}
__device__ __forceinline__ void mma16h(float* d, unsigned a0, unsigned a1, unsigned a2,
                                       unsigned a3, unsigned b0, unsigned b1) {
    asm volatile(
        "mma.sync.aligned.m16n8k16.row.col.f32.f16.f16.f32 "
        "{%0,%1,%2,%3},{%4,%5,%6,%7},{%8,%9},{%0,%1,%2,%3};"
        : "+f"(d[0]), "+f"(d[1]), "+f"(d[2]), "+f"(d[3])
        : "r"(a0), "r"(a1), "r"(a2), "r"(a3), "r"(b0), "r"(b1));
}
__device__ __forceinline__ unsigned packh2(float a, float b) {
    __half2 h = __floats2half2_rn(a, b);
    return *(unsigned*)&h;
}
__device__ __forceinline__ unsigned ld2h(const __half* base, int olo, int ohi) {
    unsigned short lo = __half_as_ushort(base[olo]);
    unsigned short hi = __half_as_ushort(base[ohi]);
    unsigned r; asm("mov.b32 %0, {%1,%2};" : "=r"(r) : "h"(lo), "h"(hi));
    return r;
}
__device__ __forceinline__ unsigned sptr(const void* p) {
    return (unsigned)__cvta_generic_to_shared(p);
}
#define CP_ASYNC8(dst, src)  asm volatile("cp.async.ca.shared.global [%0], [%1], 8;"  :: "r"(dst), "l"(src))
#define CP_ASYNC16(dst, src) asm volatile("cp.async.cg.shared.global [%0], [%1], 16;" :: "r"(dst), "l"(src))
#define CP_COMMIT            asm volatile("cp.async.commit_group;")
#define CP_WAIT(n)           asm volatile("cp.async.wait_group %0;" :: "n"(n))

// ---------------- prep ----------------
__global__ void prep_k(const float* __restrict__ w2, const float* __restrict__ pw,
                       const float* __restrict__ w1) {
    int gtid = blockIdx.x * blockDim.x + threadIdx.x;
    int stride = gridDim.x * blockDim.x;
    for (int i = gtid; i < 17024; i += stride) {   // conv2 B frags fp16, paired-k order
        int ck = i / 448, rem = i % 448, p = rem / 56, n = rem % 56;
        int P = ck * 8 + p;
        float v0 = 0.f, v1 = 0.f;
        if (P < 300 && n < 50) {
            int ic = P / 15, r2 = P % 15, kr = r2 / 3, pc = r2 % 3;
            int k0 = ic * 25 + kr * 5 + pc * 2;
            v0 = w2[n * 500 + k0];
            if (pc < 2) v1 = w2[n * 500 + k0 + 1];
        }
        g_w2fh[i] = packh2(v0, v1);
    }
    for (int i = gtid; i < 5120; i += stride) {    // pcaps A frags (tf32)
        int kc = i >> 5, lane = i & 31, g = lane >> 2, t = lane & 3;
        int k0 = kc * 8;
        float v0 = (k0 + t     < 1250) ? pw[g * 1250 + k0 + t]           : 0.f;
        float v1 = (k0 + t     < 1250) ? pw[(g + 8) * 1250 + k0 + t]     : 0.f;
        float v2 = (k0 + t + 4 < 1250) ? pw[g * 1250 + k0 + t + 4]       : 0.f;
        float v3 = (k0 + t + 4 < 1250) ? pw[(g + 8) * 1250 + k0 + t + 4] : 0.f;
        g_wpa[i] = make_uint4(f2tf(v0), f2tf(v1), f2tf(v2), f2tf(v3));
    }
    for (int i = gtid; i < 304; i += stride) {     // conv2 pair offsets
        int lo = 9216, hi = 9216;
        if (i < 300) {
            int ic = i / 15, r2 = i % 15, kr = r2 / 3, pc = r2 % 3;
            lo = ic * 448 + kr * 28 + pc * 2;
            hi = (pc < 2) ? lo + 1 : 9216;
        }
        g_koffc2[i] = make_int2(lo, hi);
    }
    for (int i = gtid; i < 640; i += stride) {     // pcaps offsets
        int k = (i >> 2) * 8 + (i & 3);
        int o0 = (k < 1250) ? (k / 25) * 160 + ((k % 25) / 5) * 16 + (k % 5) : 8000;
        int k4 = k + 4;
        int o1 = (k4 < 1250) ? (k4 / 25) * 160 + ((k4 % 25) / 5) * 16 + (k4 % 5) : 8000;
        g_koffp[i] = make_int2(o0, o1);
    }
    for (int i = gtid; i < 226 * 8 * 512; i += stride) {  // fc1 B frags fp16
        int kc = i >> 12, rem = i & 4095, p = rem >> 9, n = rem & 511;
        int k = kc * 16 + 2 * p;
        float v0 = (n < 500 && k     < 3602) ? w1[n * 3602 + k]     : 0.f;
        float v1 = (n < 500 && k + 1 < 3602) ? w1[n * 3602 + k + 1] : 0.f;
        g_w1h[i] = packh2(v0, v1);
    }
}

// ================= fused backbone =================
// dyn smem (95104 B), phase-aliased:
//   [0     ..19200)  sxth half[9600] (conv1 out fp16 + zero tail) | post-conv2: sconv f32[14400] (..57600)
//                    | pcaps: swc @8192 (..49152) | sp f32[1152] @0
//   [19200 ..53248)  sBfh0 u32[8512] (conv2 B window 0)
//   [53248 ..87296)  sBfh1 u32[8512] (window 1)   | post-conv2 tail aliased by sconv/sh2p
//   [57600 ..89984)  sh2p u32[8096] (pcaps padded input, tf32)
//   [89984 ..95104)  skoffp int2[640]
__device__ __forceinline__ float sq1(float s) { return s * fabsf(s) / (1.f + s * s); }

__global__ __launch_bounds__(288, 2) void backbone_k(
    const float* __restrict__ x, const float* __restrict__ c1w, const float* __restrict__ c1b,
    const float* __restrict__ c2b, const float* __restrict__ pcb, const float* __restrict__ rw) {
    extern __shared__ __align__(16) unsigned char cs[];
    __half*   sxth   = (__half*)cs;
    unsigned* sBfh0  = (unsigned*)(cs + 19200);
    unsigned* sBfh1  = (unsigned*)(cs + 53248);
    float*    sconv  = (float*)cs;
    float*    sp     = (float*)cs;
    uint4*    swc    = (uint4*)(cs + 8192);
    float*    sx1    = (float*)(cs + 53248);   // input stage (dead before sBfh1 load)
    unsigned* sh2p   = (unsigned*)(cs + 57600);
    int2*     skoffp = (int2*)(cs + 89984);
    __shared__ __align__(8) float sw1[640];
    __shared__ float sb1[20];
    __shared__ int2  skoffc2[304];

    int b = blockIdx.x, tid = threadIdx.x;
    int warp = tid >> 5, lane = tid & 31, g = lane >> 2, t = lane & 3;

    // ---- P0 ----
    for (int i = tid; i < 2160; i += 288) sx1[i] = x[b * 2160 + i];
    for (int i = tid; i < 640;  i += 288) {
        int oc = i >> 5, rem = i & 31;
        int r = rem / 6, c = rem % 6;
        sw1[i] = (rem < 30 && c < 5) ? c1w[oc * 25 + r * 5 + c] : 0.f;
    }
    if (tid < 20) sb1[tid] = c1b[tid];
    for (int i = tid; i < 304; i += 288) skoffc2[i] = g_koffc2[i];
    for (int i = tid; i < 640; i += 288) skoffp[i] = g_koffp[i];
    __syncthreads();

    // prefetch conv2 B window 0 (hidden behind conv1)
    for (int i = tid; i < 4256; i += 288)
        CP_ASYNC8(sptr(&sBfh0[i * 2]), &g_w2fh[i * 2]);
    CP_COMMIT;

    // ---- conv1 + pool (exact fp32) -> fp16 into sxth ----
    for (int i = tid; i < 2240; i += 288) {
        int og = i / 448, pos = i % 448;
        int ph = pos / 28, pw = pos % 28;
        int r0 = ph * 2, c0 = pw * 2;
        float patch[6][6];
#pragma unroll
        for (int pr = 0; pr < 6; pr++) {
            const float2* row = (const float2*)&sx1[(r0 + pr) * 60 + c0];
            float2 p0 = row[0], p1 = row[1], p2 = row[2];
            patch[pr][0] = p0.x; patch[pr][1] = p0.y;
            patch[pr][2] = p1.x; patch[pr][3] = p1.y;
            patch[pr][4] = p2.x; patch[pr][5] = p2.y;
        }
        int oc0 = og * 4;
#pragma unroll
        for (int o = 0; o < 4; o++) {
            const float* wp = &sw1[(oc0 + o) * 32];
            float a00 = 0, a01 = 0, a10 = 0, a11 = 0;
#pragma unroll
            for (int kr = 0; kr < 5; kr++) {
                float2 w01 = *(const float2*)&wp[kr * 6];
                float2 w23 = *(const float2*)&wp[kr * 6 + 2];
                float  w4  = wp[kr * 6 + 4];
                float wvs[5] = {w01.x, w01.y, w23.x, w23.y, w4};
#pragma unroll
                for (int kc = 0; kc < 5; kc++) {
                    float wv = wvs[kc];
                    a00 = fmaf(patch[kr][kc],         wv, a00);
                    a01 = fmaf(patch[kr][kc + 1],     wv, a01);
                    a10 = fmaf(patch[kr + 1][kc],     wv, a10);
                    a11 = fmaf(patch[kr + 1][kc + 1], wv, a11);
                }
            }
            sxth[(oc0 + o) * 448 + pos] =
                __float2half_rn(fmaxf(fmaxf(a00, a01), fmaxf(a10, a11)) + sb1[oc0 + o]);
        }
    }
    for (int i = 8960 + tid; i < 9600; i += 288) sxth[i] = __float2half_rn(0.f);
    __syncthreads();   // conv1 done; sx1 dead

    // prefetch window 1
    for (int i = tid; i < 4256; i += 288)
        CP_ASYNC8(sptr(&sBfh1[i * 2]), &g_w2fh[8512 + i * 2]);
    CP_COMMIT;
    CP_WAIT(1);
    __syncthreads();   // window 0 visible

    // ---- conv2 via fp16 mma: M=288, N=56(50), K=608(500 taps, paired order) ----
    float acc[2][7][4];
#pragma unroll
    for (int s = 0; s < 2; s++)
#pragma unroll
        for (int nt = 0; nt < 7; nt++)
#pragma unroll
            for (int q = 0; q < 4; q++) acc[s][nt][q] = 0.f;

    int pb[2][2];
#pragma unroll
    for (int s = 0; s < 2; s++) {
        int m0 = (warp * 2 + s) * 16 + g;
        pb[s][0] = (m0 / 24) * 28 + (m0 % 24);
        int m1 = m0 + 8;
        pb[s][1] = (m1 / 24) * 28 + (m1 % 24);
    }

    for (int win = 0; win < 2; win++) {
        const unsigned* sBf = win ? sBfh1 : sBfh0;
#pragma unroll 1
        for (int wk = 0; wk < 19; wk++) {
            int ck = win * 19 + wk;
            int2 kot  = skoffc2[ck * 8 + t];
            int2 kot4 = skoffc2[ck * 8 + t + 4];
            unsigned a[2][4];
#pragma unroll
            for (int s = 0; s < 2; s++) {
                a[s][0] = ld2h(sxth, pb[s][0] + kot.x,  pb[s][0] + kot.y);
                a[s][1] = ld2h(sxth, pb[s][1] + kot.x,  pb[s][1] + kot.y);
                a[s][2] = ld2h(sxth, pb[s][0] + kot4.x, pb[s][0] + kot4.y);
                a[s][3] = ld2h(sxth, pb[s][1] + kot4.x, pb[s][1] + kot4.y);
            }
#pragma unroll
            for (int nt = 0; nt < 7; nt++) {
                unsigned b0 = sBf[(wk * 8 + t) * 56 + nt * 8 + g];
                unsigned b1 = sBf[(wk * 8 + t + 4) * 56 + nt * 8 + g];
                mma16h(acc[0][nt], a[0][0], a[0][1], a[0][2], a[0][3], b0, b1);
                mma16h(acc[1][nt], a[1][0], a[1][1], a[1][2], a[1][3], b0, b1);
            }
        }
        if (win == 0) {
            CP_WAIT(0);
            __syncthreads();   // window 1 visible; also orders window-0 reads
        }
    }
    __syncthreads();   // all mma done before aliasing writes

    // ---- writeout conv2 pre-pool (sconv aliases sxth/sBfh0/sBfh1-head) ----
#pragma unroll
    for (int s = 0; s < 2; s++) {
        int m0 = (warp * 2 + s) * 16 + g;
#pragma unroll
        for (int nt = 0; nt < 7; nt++) {
            int n0 = nt * 8 + 2 * t;
            if (n0 < 50) {
                sconv[n0 * 288 + m0]     = acc[s][nt][0];
                sconv[n0 * 288 + m0 + 8] = acc[s][nt][2];
            }
            if (n0 + 1 < 50) {
                sconv[(n0 + 1) * 288 + m0]     = acc[s][nt][1];
                sconv[(n0 + 1) * 288 + m0 + 8] = acc[s][nt][3];
            }
        }
    }
    for (int i = tid; i < 8096; i += 288) sh2p[i] = 0u;
    __syncthreads();

    // ---- maxpool + bias -> tf32 smem (pcaps) + fp16 gmem (fc1) ----
    for (int i = tid; i < 3600; i += 288) {
        int oc = i / 72, rem = i % 72, ph = rem / 12, pw = rem % 12;
        const float* base = &sconv[oc * 288 + ph * 48 + pw * 2];
        float m = fmaxf(fmaxf(base[0], base[1]), fmaxf(base[24], base[25])) + c2b[oc];
        sh2p[oc * 160 + (ph + 2) * 16 + (pw + 2)] = f2tf(m);
        g_h2h[b * 3600 + i] = __float2half_rn(m);
    }
    __syncthreads();   // sconv dead; swc region free

    // ---- stage pcaps weights through smem: 4 chunks x 40kc (20KB), double-buffered ----
    for (int i = tid; i < 1280; i += 288)
        CP_ASYNC16(sptr(&swc[i]), &g_wpa[i]);
    CP_COMMIT;
    for (int i = tid; i < 1280; i += 288)
        CP_ASYNC16(sptr(&swc[1280 + i]), &g_wpa[1280 + i]);
    CP_COMMIT;

    // ---- pcaps via tf32 mma (unchanged) ----
    {
        int nt = warp;
        int p = nt * 8 + g;
        int pbase = (p / 12) * 16 + (p % 12);
        float pa4[4][4];
#pragma unroll
        for (int c = 0; c < 4; c++)
#pragma unroll
            for (int q = 0; q < 4; q++) pa4[c][q] = 0.f;

        for (int ch = 0; ch < 4; ch++) {
            if (ch < 3) { CP_WAIT(1); } else { CP_WAIT(0); }
            __syncthreads();
            const uint4* wbuf = &swc[(ch & 1) * 1280];
#pragma unroll 4
            for (int j = 0; j < 40; j++) {
                int kc = ch * 40 + j;
                uint4 aa = wbuf[j * 32 + lane];
                int2 ko = skoffp[kc * 4 + t];
                unsigned b0 = sh2p[ko.x + pbase];
                unsigned b1 = sh2p[ko.y + pbase];
                mma8(pa4[kc & 3], aa.x, aa.y, aa.z, aa.w, b0, b1);
            }
            __syncthreads();
            if (ch + 2 < 4) {
                for (int i = tid; i < 1280; i += 288)
                    CP_ASYNC16(sptr(&swc[(ch & 1) * 1280 + i]), &g_wpa[(ch + 2) * 1280 + i]);
                CP_COMMIT;
            }
        }
        float pa[4];
#pragma unroll
        for (int q = 0; q < 4; q++)
            pa[q] = (pa4[0][q] + pa4[1][q]) + (pa4[2][q] + pa4[3][q]);

        int oc0 = g;
        int n0 = nt * 8 + 2 * t;
        float bsA = pcb[oc0], bsB = pcb[oc0 + 8];
        sp[oc0 * 72 + n0]           = pa[0] + bsA;
        sp[oc0 * 72 + n0 + 1]       = pa[1] + bsA;
        sp[(oc0 + 8) * 72 + n0]     = pa[2] + bsB;
        sp[(oc0 + 8) * 72 + n0 + 1] = pa[3] + bsB;
    }
    __syncthreads();

    // ---- squash + priors + 3-iter routing ----
    if (warp < 2) {
        int k = warp;
        float pr[9];
#pragma unroll
        for (int j = 0; j < 9; j++) {
            int r = lane + 32 * j;
            int cw = r / 72, hw = r % 72;
            const float* pbp = sp + cw * 72 + hw;
            float u0 = pbp[0], u1 = pbp[288], u2 = pbp[576], u3 = pbp[864];
            float n2 = u0 * u0 + u1 * u1 + u2 * u2 + u3 * u3;
            float f = sqrtf(n2) / (1.f + n2);
            float4 w4 = *(const float4*)&rw[(k * 288 + r) * 4];
            pr[j] = f * (u0 * w4.x + u1 * w4.y + u2 * w4.z + u3 * w4.w);
        }
        float S = 0.f;
#pragma unroll
        for (int j = 0; j < 9; j++) S += pr[j];
#pragma unroll
        for (int o = 16; o; o >>= 1) S += __shfl_xor_sync(0xffffffffu, S, o);
        float s = S * (1.f / 288.f);
        float v = sq1(s);
        float vsum = v;
#pragma unroll
        for (int it = 0; it < 2; it++) {
            float m = -1e30f;
#pragma unroll
            for (int j = 0; j < 9; j++) m = fmaxf(m, pr[j] * vsum);
#pragma unroll
            for (int o = 16; o; o >>= 1) m = fmaxf(m, __shfl_xor_sync(0xffffffffu, m, o));
            float Z = 0.f, T = 0.f;
#pragma unroll
            for (int j = 0; j < 9; j++) {
                float e = __expf(pr[j] * vsum - m);
                Z += e;
                T = fmaf(e, pr[j], T);
            }
#pragma unroll
            for (int o = 16; o; o >>= 1) {
                Z += __shfl_xor_sync(0xffffffffu, Z, o);
                T += __shfl_xor_sync(0xffffffffu, T, o);
            }
            float s2 = T / Z;
            v = sq1(s2);
            vsum += v;
        }
        if (lane == 0) g_c[b * 2 + k] = v;
    }
}

// ---------------- fc1 split-K fp16: CTA tile 128m x 128n, Ksplit=4, m16n8k16 ----------------
__global__ __launch_bounds__(256) void fc1_mma_k() {
    extern __shared__ __align__(16) unsigned char ds[];
    __half*   As = (__half*)ds;
    unsigned* Bh = (unsigned*)(ds + 30720);
    const int ASTR = 128 * 40;
    const int BSTR = 16 * 132;

    int n0 = blockIdx.x * 128, m0 = blockIdx.y * 128;
    int ks = blockIdx.z;
    int ktb = (113 * ks) >> 2;
    int kte = (113 * (ks + 1)) >> 2;
    int tid = threadIdx.x, warp = tid >> 5, lane = tid & 31, g = lane >> 2, t = lane & 3;

    float acc[16][4];
#pragma unroll
    for (int nt = 0; nt < 16; nt++)
#pragma unroll
        for (int q = 0; q < 4; q++) acc[nt][q] = 0.f;

    auto stage = [&](int kt, int buf) {
        __half* A = &As[buf * ASTR];
        int rowA = tid >> 1, halfA = tid & 1;
        if (kt < 112) {
            const __half* src = &g_h2h[(m0 + rowA) * 3600 + kt * 32 + halfA * 16];
            unsigned d0 = sptr(&A[rowA * 40 + halfA * 16]);
            CP_ASYNC16(d0, src);
            CP_ASYNC16(d0 + 16, src + 8);
        } else {
            if (halfA == 0) {
#pragma unroll
                for (int q = 0; q < 16; q++)
                    A[rowA * 40 + q] = g_h2h[(m0 + rowA) * 3600 + 3584 + q];
            } else {
#pragma unroll
                for (int q = 0; q < 16; q++) {
                    int k = 3600 + q;
                    __half v = __float2half_rn(0.f);
                    if (k < 3602) v = __float2half_rn(g_c[(m0 + rowA) * 2 + (k - 3600)]);
                    A[rowA * 40 + 16 + q] = v;
                }
            }
        }
        unsigned* B = &Bh[buf * BSTR];
        int rowB = tid >> 4, offB = (tid & 15) * 8;
        unsigned dB = sptr(&B[rowB * 132 + offB]);
        const unsigned* sB = &g_w1h[(kt * 16 + rowB) * 512 + n0 + offB];
        CP_ASYNC16(dB, sB);
        CP_ASYNC16(dB + 16, sB + 4);
        CP_COMMIT;
    };

    stage(ktb,     0);
    stage(ktb + 1, 1);

    int buf = 0;
    for (int kt = ktb; kt < kte; kt++) {
        if (kt + 1 < kte) { CP_WAIT(1); } else { CP_WAIT(0); }
        __syncthreads();
        const unsigned* Au = (const unsigned*)&As[buf * ASTR];
        const unsigned* B  = &Bh[buf * BSTR];
        int r0 = warp * 16 + g;
#pragma unroll
        for (int c = 0; c < 2; c++) {
            unsigned a0 = Au[r0 * 20 + c * 8 + t];
            unsigned a1 = Au[(r0 + 8) * 20 + c * 8 + t];
            unsigned a2 = Au[r0 * 20 + c * 8 + t + 4];
            unsigned a3 = Au[(r0 + 8) * 20 + c * 8 + t + 4];
#pragma unroll
            for (int nt = 0; nt < 16; nt++) {
                unsigned b0 = B[(c * 8 + t) * 132 + nt * 8 + g];
                unsigned b1 = B[(c * 8 + t + 4) * 132 + nt * 8 + g];
                mma16h(acc[nt], a0, a1, a2, a3, b0, b1);
            }
        }
        if (kt + 2 < kte) stage(kt + 2, (buf + 2) % 3);
        buf = (buf == 2) ? 0 : buf + 1;
    }

    float* dst = &g_fp[(size_t)ks * NB * 512];
    int mrow = m0 + warp * 16 + g;
#pragma unroll
    for (int nt = 0; nt < 16; nt++) {
        int n = n0 + nt * 8 + 2 * t;
        dst[mrow * 512 + n]           = acc[nt][0];
        dst[mrow * 512 + n + 1]       = acc[nt][1];
        dst[(mrow + 8) * 512 + n]     = acc[nt][2];
        dst[(mrow + 8) * 512 + n + 1] = acc[nt][3];
    }
}

// ---------------- fused fc1-reduce + fc2 ----------------
__global__ __launch_bounds__(256) void fc2_k(
    const float* __restrict__ y, const float* __restrict__ f1b,
    const float* __restrict__ w2, const float* __restrict__ b2, float* __restrict__ out) {
    const int S = NB * 512;
    int b = (blockIdx.x * blockDim.x + threadIdx.x) >> 5;
    int lane = threadIdx.x & 31;
    const float* w0 = w2;
    const float* w1 = w2 + 502;
    float a0 = 0.f, a1 = 0.f;
    for (int i4 = lane; i4 < 125; i4 += 32) {
        int j = i4 * 4, o = b * 512 + j;
        float4 p0 = *(const float4*)&g_fp[o];
        float4 p1 = *(const float4*)&g_fp[S + o];
        float4 p2 = *(const float4*)&g_fp[2 * S + o];
        float4 p3 = *(const float4*)&g_fp[3 * S + o];
        float4 bi = *(const float4*)&f1b[j];
        float4 wv = *(const float4*)&w0[j];
        float v0 = fmaxf((p0.x + p1.x) + (p2.x + p3.x) + bi.x, 0.f);
        float v1 = fmaxf((p0.y + p1.y) + (p2.y + p3.y) + bi.y, 0.f);
        float v2 = fmaxf((p0.z + p1.z) + (p2.z + p3.z) + bi.z, 0.f);
        float v3 = fmaxf((p0.w + p1.w) + (p2.w + p3.w) + bi.w, 0.f);
        a0 = fmaf(v0, wv.x, a0); a0 = fmaf(v1, wv.y, a0);
        a0 = fmaf(v2, wv.z, a0); a0 = fmaf(v3, wv.w, a0);
        a1 = fmaf(v0, w1[j],     a1); a1 = fmaf(v1, w1[j + 1], a1);
        a1 = fmaf(v2, w1[j + 2], a1); a1 = fmaf(v3, w1[j + 3], a1);
    }
    if (lane == 0) {
        float y0 = y[b * 2], y1 = y[b * 2 + 1];
        a0 += w0[500] * y0 + w0[501] * y1 + b2[0];
        a1 += w1[500] * y0 + w1[501] * y1 + b2[1];
    }
#pragma unroll
    for (int off = 16; off; off >>= 1) {
        a0 += __shfl_xor_sync(0xffffffffu, a0, off);
        a1 += __shfl_xor_sync(0xffffffffu, a1, off);
    }
    if (lane == 0) {
        out[b * 2]     = a0;
        out[b * 2 + 1] = a1;
    }
}

// ---------------- launch ----------------
extern "C" void kernel_launch(void* const* d_in, const int* in_sizes, int n_in,
                              void* d_out, int out_size) {
    const float* x   = (const float*)d_in[0];
    const float* y   = (const float*)d_in[1];
    const float* c1w = (const float*)d_in[2];
    const float* c1b = (const float*)d_in[3];
    const float* c2w = (const float*)d_in[4];
    const float* c2b = (const float*)d_in[5];
    const float* pw  = (const float*)d_in[6];
    const float* pb  = (const float*)d_in[7];
    const float* rw  = (const float*)d_in[8];
    const float* f1w = (const float*)d_in[9];
    const float* f1b = (const float*)d_in[10];
    const float* f2w = (const float*)d_in[11];
    const float* f2b = (const float*)d_in[12];
    float* out = (float*)d_out;

    const int bb_smem  = 95104;
    const int fc1_smem = 56064;
    cudaFuncSetAttribute(backbone_k, cudaFuncAttributeMaxDynamicSharedMemorySize, bb_smem);
    cudaFuncSetAttribute(fc1_mma_k,  cudaFuncAttributeMaxDynamicSharedMemorySize, fc1_smem);

    prep_k<<<512, 256>>>(c2w, pw, f1w);
    backbone_k<<<NB, 288, bb_smem>>>(x, c1w, c1b, c2b, pb, rw);
    dim3 g4(4, 16, 4);
    fc1_mma_k<<<g4, 256, fc1_smem>>>();
    fc2_k<<<NB / 8, 256>>>(y, f1b, f2w, f2b, out);
}

// round 15
// speedup vs baseline: 1.5204x; 1.0184x over previous
#include <cuda_runtime.h>
#include <cuda_fp16.h>
#include <math.h>
#include <stdint.h>

#define NB 2048

// ---------------- scratch (device globals; no allocation) ----------------
__device__ __half g_h2h[NB * 3600];         // conv2+pool out (fp16 == tf32 grid) [b][3600]
__device__ float g_c [NB * 2];              // routed capsule outputs
__device__ float g_fp[4 * NB * 512];        // fc1 split-K partials [s][m][n(512)]
__device__ unsigned g_w2fh[38 * 8 * 56];    // conv2 B frags fp16: [chunk][pair][n] half2
__device__ uint4 g_wpah[96 * 32];           // pcaps A frags fp16: [chunk][lane] 4x half2
__device__ unsigned g_w1h[226 * 8 * 512];   // fc1 B frags fp16: [kc16][p][n] half2
__device__ int2  g_koffc2[304];             // conv2 pair offsets {lo,hi} (zero slot 9216)
__device__ int2  g_koffp2[768];             // pcaps pair offsets {lo,hi} (zero slot 8000)

// ---------------- helpers ----------------
__device__ __forceinline__ void mma16h(float* d, unsigned a0, unsigned a1, unsigned a2,
                                       unsigned a3, unsigned b0, unsigned b1) {
    asm volatile(
        "mma.sync.aligned.m16n8k16.row.col.f32.f16.f16.f32 "
        "{%0,%1,%2,%3},{%4,%5,%6,%7},{%8,%9},{%0,%1,%2,%3};"
        : "+f"(d[0]), "+f"(d[1]), "+f"(d[2]), "+f"(d[3])
        : "r"(a0), "r"(a1), "r"(a2), "r"(a3), "r"(b0), "r"(b1));
}
__device__ __forceinline__ unsigned packh2(float a, float b) {
    __half2 h = __floats2half2_rn(a, b);
    return *(unsigned*)&h;
}
__device__ __forceinline__ unsigned ld2h(const __half* base, int olo, int ohi) {
    unsigned short lo = __half_as_ushort(base[olo]);
    unsigned short hi = __half_as_ushort(base[ohi]);
    unsigned r; asm("mov.b32 %0, {%1,%2};" : "=r"(r) : "h"(lo), "h"(hi));
    return r;
}
__device__ __forceinline__ unsigned sptr(const void* p) {
    return (unsigned)__cvta_generic_to_shared(p);
}
#define CP_ASYNC8(dst, src)  asm volatile("cp.async.ca.shared.global [%0], [%1], 8;"  :: "r"(dst), "l"(src))
#define CP_ASYNC16(dst, src) asm volatile("cp.async.cg.shared.global [%0], [%1], 16;" :: "r"(dst), "l"(src))
#define CP_COMMIT            asm volatile("cp.async.commit_group;")
#define CP_WAIT(n)           asm volatile("cp.async.wait_group %0;" :: "n"(n))

// ---------------- prep ----------------
__global__ void prep_k(const float* __restrict__ w2, const float* __restrict__ pw,
                       const float* __restrict__ w1) {
    int gtid = blockIdx.x * blockDim.x + threadIdx.x;
    int stride = gridDim.x * blockDim.x;
    for (int i = gtid; i < 17024; i += stride) {   // conv2 B frags fp16, paired-k order
        int ck = i / 448, rem = i % 448, p = rem / 56, n = rem % 56;
        int P = ck * 8 + p;
        float v0 = 0.f, v1 = 0.f;
        if (P < 300 && n < 50) {
            int ic = P / 15, r2 = P % 15, kr = r2 / 3, pc = r2 % 3;
            int k0 = ic * 25 + kr * 5 + pc * 2;
            v0 = w2[n * 500 + k0];
            if (pc < 2) v1 = w2[n * 500 + k0 + 1];
        }
        g_w2fh[i] = packh2(v0, v1);
    }
    for (int i = gtid; i < 3072; i += stride) {    // pcaps A frags fp16, paired-k order
        int ck = i >> 5, lane = i & 31, g = lane >> 2, t = lane & 3;
        auto wp2 = [&](int row, int P) -> unsigned {
            float v0 = 0.f, v1 = 0.f;
            if (P < 750) {
                int ic = P / 15, r2 = P % 15, kr = r2 / 3, pc = r2 % 3;
                int k0 = ic * 25 + kr * 5 + pc * 2;
                v0 = pw[row * 1250 + k0];
                if (pc < 2) v1 = pw[row * 1250 + k0 + 1];
            }
            return packh2(v0, v1);
        };
        g_wpah[i] = make_uint4(wp2(g, ck * 8 + t), wp2(g + 8, ck * 8 + t),
                               wp2(g, ck * 8 + t + 4), wp2(g + 8, ck * 8 + t + 4));
    }
    for (int i = gtid; i < 304; i += stride) {     // conv2 pair offsets
        int lo = 9216, hi = 9216;
        if (i < 300) {
            int ic = i / 15, r2 = i % 15, kr = r2 / 3, pc = r2 % 3;
            lo = ic * 448 + kr * 28 + pc * 2;
            hi = (pc < 2) ? lo + 1 : 9216;
        }
        g_koffc2[i] = make_int2(lo, hi);
    }
    for (int i = gtid; i < 768; i += stride) {     // pcaps pair offsets
        int lo = 8000, hi = 8000;
        if (i < 750) {
            int ic = i / 15, r2 = i % 15, kr = r2 / 3, pc = r2 % 3;
            lo = ic * 160 + kr * 16 + pc * 2;
            hi = (pc < 2) ? lo + 1 : 8000;
        }
        g_koffp2[i] = make_int2(lo, hi);
    }
    for (int i = gtid; i < 226 * 8 * 512; i += stride) {  // fc1 B frags fp16
        int kc = i >> 12, rem = i & 4095, p = rem >> 9, n = rem & 511;
        int k = kc * 16 + 2 * p;
        float v0 = (n < 500 && k     < 3602) ? w1[n * 3602 + k]     : 0.f;
        float v1 = (n < 500 && k + 1 < 3602) ? w1[n * 3602 + k + 1] : 0.f;
        g_w1h[i] = packh2(v0, v1);
    }
}

// ================= fused backbone =================
// dyn smem (93440 B), phase-aliased:
//   [0     ..19200)  sxth half[9600]  | post-conv2: sconv f32[14400] (0..57600) | sp f32[1152] @0
//   [8192  ..32768)  swc uint4[2][768] (pcaps A stage; alive only during pcaps, inside dead sconv)
//   [19200 ..53248)  sBfh0 u32[8512]
//   [53248 ..87296)  sBfh1 u32[8512]  | phase0 alias: sx1 f32[2160] @53248
//   [57600 ..73984)  sh2ph half[8192] (pcaps padded image fp16; written post-conv2)
//   [87296 ..93440)  skoffp2 int2[768]
__device__ __forceinline__ float sq1(float s) { return s * fabsf(s) / (1.f + s * s); }

__global__ __launch_bounds__(288, 2) void backbone_k(
    const float* __restrict__ x, const float* __restrict__ c1w, const float* __restrict__ c1b,
    const float* __restrict__ c2b, const float* __restrict__ pcb, const float* __restrict__ rw) {
    extern __shared__ __align__(16) unsigned char cs[];
    __half*   sxth   = (__half*)cs;
    unsigned* sBfh0  = (unsigned*)(cs + 19200);
    unsigned* sBfh1  = (unsigned*)(cs + 53248);
    float*    sconv  = (float*)cs;
    float*    sp     = (float*)cs;
    uint4*    swc    = (uint4*)(cs + 8192);
    float*    sx1    = (float*)(cs + 53248);
    __half*   sh2ph  = (__half*)(cs + 57600);
    int2*     skoffp2 = (int2*)(cs + 87296);
    __shared__ __align__(8) float sw1[640];
    __shared__ float sb1[20];
    __shared__ int2  skoffc2[304];

    int b = blockIdx.x, tid = threadIdx.x;
    int warp = tid >> 5, lane = tid & 31, g = lane >> 2, t = lane & 3;

    // ---- P0 ----
    for (int i = tid; i < 2160; i += 288) sx1[i] = x[b * 2160 + i];
    for (int i = tid; i < 640;  i += 288) {
        int oc = i >> 5, rem = i & 31;
        int r = rem / 6, c = rem % 6;
        sw1[i] = (rem < 30 && c < 5) ? c1w[oc * 25 + r * 5 + c] : 0.f;
    }
    if (tid < 20) sb1[tid] = c1b[tid];
    for (int i = tid; i < 304; i += 288) skoffc2[i] = g_koffc2[i];
    for (int i = tid; i < 768; i += 288) skoffp2[i] = g_koffp2[i];
    __syncthreads();

    // prefetch conv2 B window 0 (hidden behind conv1)
    for (int i = tid; i < 4256; i += 288)
        CP_ASYNC8(sptr(&sBfh0[i * 2]), &g_w2fh[i * 2]);
    CP_COMMIT;

    // ---- conv1 + pool (exact fp32) -> fp16 into sxth ----
    for (int i = tid; i < 2240; i += 288) {
        int og = i / 448, pos = i % 448;
        int ph = pos / 28, pw = pos % 28;
        int r0 = ph * 2, c0 = pw * 2;
        float patch[6][6];
#pragma unroll
        for (int pr = 0; pr < 6; pr++) {
            const float2* row = (const float2*)&sx1[(r0 + pr) * 60 + c0];
            float2 p0 = row[0], p1 = row[1], p2 = row[2];
            patch[pr][0] = p0.x; patch[pr][1] = p0.y;
            patch[pr][2] = p1.x; patch[pr][3] = p1.y;
            patch[pr][4] = p2.x; patch[pr][5] = p2.y;
        }
        int oc0 = og * 4;
#pragma unroll
        for (int o = 0; o < 4; o++) {
            const float* wp = &sw1[(oc0 + o) * 32];
            float a00 = 0, a01 = 0, a10 = 0, a11 = 0;
#pragma unroll
            for (int kr = 0; kr < 5; kr++) {
                float2 w01 = *(const float2*)&wp[kr * 6];
                float2 w23 = *(const float2*)&wp[kr * 6 + 2];
                float  w4  = wp[kr * 6 + 4];
                float wvs[5] = {w01.x, w01.y, w23.x, w23.y, w4};
#pragma unroll
                for (int kc = 0; kc < 5; kc++) {
                    float wv = wvs[kc];
                    a00 = fmaf(patch[kr][kc],         wv, a00);
                    a01 = fmaf(patch[kr][kc + 1],     wv, a01);
                    a10 = fmaf(patch[kr + 1][kc],     wv, a10);
                    a11 = fmaf(patch[kr + 1][kc + 1], wv, a11);
                }
            }
            sxth[(oc0 + o) * 448 + pos] =
                __float2half_rn(fmaxf(fmaxf(a00, a01), fmaxf(a10, a11)) + sb1[oc0 + o]);
        }
    }
    for (int i = 8960 + tid; i < 9600; i += 288) sxth[i] = __float2half_rn(0.f);
    __syncthreads();   // conv1 done; sx1 dead

    // prefetch window 1
    for (int i = tid; i < 4256; i += 288)
        CP_ASYNC8(sptr(&sBfh1[i * 2]), &g_w2fh[8512 + i * 2]);
    CP_COMMIT;
    CP_WAIT(1);
    __syncthreads();   // window 0 visible

    // ---- conv2 via fp16 mma: M=288, N=56(50), K=608(500 taps, paired order) ----
    float acc[2][7][4];
#pragma unroll
    for (int s = 0; s < 2; s++)
#pragma unroll
        for (int nt = 0; nt < 7; nt++)
#pragma unroll
            for (int q = 0; q < 4; q++) acc[s][nt][q] = 0.f;

    int pb[2][2];
#pragma unroll
    for (int s = 0; s < 2; s++) {
        int m0 = (warp * 2 + s) * 16 + g;
        pb[s][0] = (m0 / 24) * 28 + (m0 % 24);
        int m1 = m0 + 8;
        pb[s][1] = (m1 / 24) * 28 + (m1 % 24);
    }

    for (int win = 0; win < 2; win++) {
        const unsigned* sBf = win ? sBfh1 : sBfh0;
#pragma unroll 1
        for (int wk = 0; wk < 19; wk++) {
            int ck = win * 19 + wk;
            int2 kot  = skoffc2[ck * 8 + t];
            int2 kot4 = skoffc2[ck * 8 + t + 4];
            unsigned a[2][4];
#pragma unroll
            for (int s = 0; s < 2; s++) {
                a[s][0] = ld2h(sxth, pb[s][0] + kot.x,  pb[s][0] + kot.y);
                a[s][1] = ld2h(sxth, pb[s][1] + kot.x,  pb[s][1] + kot.y);
                a[s][2] = ld2h(sxth, pb[s][0] + kot4.x, pb[s][0] + kot4.y);
                a[s][3] = ld2h(sxth, pb[s][1] + kot4.x, pb[s][1] + kot4.y);
            }
#pragma unroll
            for (int nt = 0; nt < 7; nt++) {
                unsigned b0 = sBf[(wk * 8 + t) * 56 + nt * 8 + g];
                unsigned b1 = sBf[(wk * 8 + t + 4) * 56 + nt * 8 + g];
                mma16h(acc[0][nt], a[0][0], a[0][1], a[0][2], a[0][3], b0, b1);
                mma16h(acc[1][nt], a[1][0], a[1][1], a[1][2], a[1][3], b0, b1);
            }
        }
        if (win == 0) {
            CP_WAIT(0);
            __syncthreads();
        }
    }
    __syncthreads();   // all mma done before aliasing writes

    // ---- writeout conv2 pre-pool (sconv aliases sxth/sBfh0) ----
#pragma unroll
    for (int s = 0; s < 2; s++) {
        int m0 = (warp * 2 + s) * 16 + g;
#pragma unroll
        for (int nt = 0; nt < 7; nt++) {
            int n0 = nt * 8 + 2 * t;
            if (n0 < 50) {
                sconv[n0 * 288 + m0]     = acc[s][nt][0];
                sconv[n0 * 288 + m0 + 8] = acc[s][nt][2];
            }
            if (n0 + 1 < 50) {
                sconv[(n0 + 1) * 288 + m0]     = acc[s][nt][1];
                sconv[(n0 + 1) * 288 + m0 + 8] = acc[s][nt][3];
            }
        }
    }
    for (int i = tid; i < 8192; i += 288) sh2ph[i] = __float2half_rn(0.f);
    __syncthreads();

    // ---- maxpool + bias -> fp16 smem (pcaps) + fp16 gmem (fc1) ----
    for (int i = tid; i < 3600; i += 288) {
        int oc = i / 72, rem = i % 72, ph = rem / 12, pw = rem % 12;
        const float* base = &sconv[oc * 288 + ph * 48 + pw * 2];
        float m = fmaxf(fmaxf(base[0], base[1]), fmaxf(base[24], base[25])) + c2b[oc];
        __half hm = __float2half_rn(m);
        sh2ph[oc * 160 + (ph + 2) * 16 + (pw + 2)] = hm;
        g_h2h[b * 3600 + i] = hm;
    }
    __syncthreads();   // sconv dead; swc region free

    // ---- stage pcaps A frags: 4 stages x 24 chunks (12288 B), double-buffered ----
    for (int i = tid; i < 768; i += 288)
        CP_ASYNC16(sptr(&swc[i]), &g_wpah[i]);
    CP_COMMIT;
    for (int i = tid; i < 768; i += 288)
        CP_ASYNC16(sptr(&swc[768 + i]), &g_wpah[768 + i]);
    CP_COMMIT;

    // ---- pcaps via fp16 mma: M=16(oc), N=72, K=1536(1250 taps, paired), 4 acc chains ----
    {
        int nt = warp;
        int p = nt * 8 + g;
        int pbase = (p / 12) * 16 + (p % 12);
        float pa4[4][4];
#pragma unroll
        for (int c = 0; c < 4; c++)
#pragma unroll
            for (int q = 0; q < 4; q++) pa4[c][q] = 0.f;

        for (int st = 0; st < 4; st++) {
            if (st < 3) { CP_WAIT(1); } else { CP_WAIT(0); }
            __syncthreads();
            const uint4* wbuf = &swc[(st & 1) * 768];
#pragma unroll 4
            for (int j = 0; j < 24; j++) {
                int ck = st * 24 + j;
                uint4 aa = wbuf[j * 32 + lane];
                int2 kt_ = skoffp2[ck * 8 + t];
                int2 kt4 = skoffp2[ck * 8 + t + 4];
                unsigned b0 = ld2h(sh2ph, kt_.x + pbase, kt_.y + pbase);
                unsigned b1 = ld2h(sh2ph, kt4.x + pbase, kt4.y + pbase);
                mma16h(pa4[ck & 3], aa.x, aa.y, aa.z, aa.w, b0, b1);
            }
            __syncthreads();
            if (st + 2 < 4) {
                for (int i = tid; i < 768; i += 288)
                    CP_ASYNC16(sptr(&swc[(st & 1) * 768 + i]), &g_wpah[(st + 2) * 768 + i]);
                CP_COMMIT;
            }
        }
        float pa[4];
#pragma unroll
        for (int q = 0; q < 4; q++)
            pa[q] = (pa4[0][q] + pa4[1][q]) + (pa4[2][q] + pa4[3][q]);

        int oc0 = g;
        int n0 = nt * 8 + 2 * t;
        float bsA = pcb[oc0], bsB = pcb[oc0 + 8];
        sp[oc0 * 72 + n0]           = pa[0] + bsA;
        sp[oc0 * 72 + n0 + 1]       = pa[1] + bsA;
        sp[(oc0 + 8) * 72 + n0]     = pa[2] + bsB;
        sp[(oc0 + 8) * 72 + n0 + 1] = pa[3] + bsB;
    }
    __syncthreads();

    // ---- squash + priors + 3-iter routing ----
    if (warp < 2) {
        int k = warp;
        float pr[9];
#pragma unroll
        for (int j = 0; j < 9; j++) {
            int r = lane + 32 * j;
            int cw = r / 72, hw = r % 72;
            const float* pbp = sp + cw * 72 + hw;
            float u0 = pbp[0], u1 = pbp[288], u2 = pbp[576], u3 = pbp[864];
            float n2 = u0 * u0 + u1 * u1 + u2 * u2 + u3 * u3;
            float f = sqrtf(n2) / (1.f + n2);
            float4 w4 = *(const float4*)&rw[(k * 288 + r) * 4];
            pr[j] = f * (u0 * w4.x + u1 * w4.y + u2 * w4.z + u3 * w4.w);
        }
        float S = 0.f;
#pragma unroll
        for (int j = 0; j < 9; j++) S += pr[j];
#pragma unroll
        for (int o = 16; o; o >>= 1) S += __shfl_xor_sync(0xffffffffu, S, o);
        float s = S * (1.f / 288.f);
        float v = sq1(s);
        float vsum = v;
#pragma unroll
        for (int it = 0; it < 2; it++) {
            float m = -1e30f;
#pragma unroll
            for (int j = 0; j < 9; j++) m = fmaxf(m, pr[j] * vsum);
#pragma unroll
            for (int o = 16; o; o >>= 1) m = fmaxf(m, __shfl_xor_sync(0xffffffffu, m, o));
            float Z = 0.f, T = 0.f;
#pragma unroll
            for (int j = 0; j < 9; j++) {
                float e = __expf(pr[j] * vsum - m);
                Z += e;
                T = fmaf(e, pr[j], T);
            }
#pragma unroll
            for (int o = 16; o; o >>= 1) {
                Z += __shfl_xor_sync(0xffffffffu, Z, o);
                T += __shfl_xor_sync(0xffffffffu, T, o);
            }
            float s2 = T / Z;
            v = sq1(s2);
            vsum += v;
        }
        if (lane == 0) g_c[b * 2 + k] = v;
    }
}

// ---------------- fc1 split-K fp16: CTA tile 128m x 128n, Ksplit=4, m16n8k16 ----------------
__global__ __launch_bounds__(256) void fc1_mma_k() {
    extern __shared__ __align__(16) unsigned char ds[];
    __half*   As = (__half*)ds;
    unsigned* Bh = (unsigned*)(ds + 30720);
    const int ASTR = 128 * 40;
    const int BSTR = 16 * 132;

    int n0 = blockIdx.x * 128, m0 = blockIdx.y * 128;
    int ks = blockIdx.z;
    int ktb = (113 * ks) >> 2;
    int kte = (113 * (ks + 1)) >> 2;
    int tid = threadIdx.x, warp = tid >> 5, lane = tid & 31, g = lane >> 2, t = lane & 3;

    float acc[16][4];
#pragma unroll
    for (int nt = 0; nt < 16; nt++)
#pragma unroll
        for (int q = 0; q < 4; q++) acc[nt][q] = 0.f;

    auto stage = [&](int kt, int buf) {
        __half* A = &As[buf * ASTR];
        int rowA = tid >> 1, halfA = tid & 1;
        if (kt < 112) {
            const __half* src = &g_h2h[(m0 + rowA) * 3600 + kt * 32 + halfA * 16];
            unsigned d0 = sptr(&A[rowA * 40 + halfA * 16]);
            CP_ASYNC16(d0, src);
            CP_ASYNC16(d0 + 16, src + 8);
        } else {
            if (halfA == 0) {
#pragma unroll
                for (int q = 0; q < 16; q++)
                    A[rowA * 40 + q] = g_h2h[(m0 + rowA) * 3600 + 3584 + q];
            } else {
#pragma unroll
                for (int q = 0; q < 16; q++) {
                    int k = 3600 + q;
                    __half v = __float2half_rn(0.f);
                    if (k < 3602) v = __float2half_rn(g_c[(m0 + rowA) * 2 + (k - 3600)]);
                    A[rowA * 40 + 16 + q] = v;
                }
            }
        }
        unsigned* B = &Bh[buf * BSTR];
        int rowB = tid >> 4, offB = (tid & 15) * 8;
        unsigned dB = sptr(&B[rowB * 132 + offB]);
        const unsigned* sB = &g_w1h[(kt * 16 + rowB) * 512 + n0 + offB];
        CP_ASYNC16(dB, sB);
        CP_ASYNC16(dB + 16, sB + 4);
        CP_COMMIT;
    };

    stage(ktb,     0);
    stage(ktb + 1, 1);

    int buf = 0;
    for (int kt = ktb; kt < kte; kt++) {
        if (kt + 1 < kte) { CP_WAIT(1); } else { CP_WAIT(0); }
        __syncthreads();
        const unsigned* Au = (const unsigned*)&As[buf * ASTR];
        const unsigned* B  = &Bh[buf * BSTR];
        int r0 = warp * 16 + g;
#pragma unroll
        for (int c = 0; c < 2; c++) {
            unsigned a0 = Au[r0 * 20 + c * 8 + t];
            unsigned a1 = Au[(r0 + 8) * 20 + c * 8 + t];
            unsigned a2 = Au[r0 * 20 + c * 8 + t + 4];
            unsigned a3 = Au[(r0 + 8) * 20 + c * 8 + t + 4];
#pragma unroll
            for (int nt = 0; nt < 16; nt++) {
                unsigned b0 = B[(c * 8 + t) * 132 + nt * 8 + g];
                unsigned b1 = B[(c * 8 + t + 4) * 132 + nt * 8 + g];
                mma16h(acc[nt], a0, a1, a2, a3, b0, b1);
            }
        }
        if (kt + 2 < kte) stage(kt + 2, (buf + 2) % 3);
        buf = (buf == 2) ? 0 : buf + 1;
    }

    float* dst = &g_fp[(size_t)ks * NB * 512];
    int mrow = m0 + warp * 16 + g;
#pragma unroll
    for (int nt = 0; nt < 16; nt++) {
        int n = n0 + nt * 8 + 2 * t;
        dst[mrow * 512 + n]           = acc[nt][0];
        dst[mrow * 512 + n + 1]       = acc[nt][1];
        dst[(mrow + 8) * 512 + n]     = acc[nt][2];
        dst[(mrow + 8) * 512 + n + 1] = acc[nt][3];
    }
}

// ---------------- fused fc1-reduce + fc2 ----------------
__global__ __launch_bounds__(256) void fc2_k(
    const float* __restrict__ y, const float* __restrict__ f1b,
    const float* __restrict__ w2, const float* __restrict__ b2, float* __restrict__ out) {
    const int S = NB * 512;
    int b = (blockIdx.x * blockDim.x + threadIdx.x) >> 5;
    int lane = threadIdx.x & 31;
    const float* w0 = w2;
    const float* w1 = w2 + 502;
    float a0 = 0.f, a1 = 0.f;
    for (int i4 = lane; i4 < 125; i4 += 32) {
        int j = i4 * 4, o = b * 512 + j;
        float4 p0 = *(const float4*)&g_fp[o];
        float4 p1 = *(const float4*)&g_fp[S + o];
        float4 p2 = *(const float4*)&g_fp[2 * S + o];
        float4 p3 = *(const float4*)&g_fp[3 * S + o];
        float4 bi = *(const float4*)&f1b[j];
        float4 wv = *(const float4*)&w0[j];
        float v0 = fmaxf((p0.x + p1.x) + (p2.x + p3.x) + bi.x, 0.f);
        float v1 = fmaxf((p0.y + p1.y) + (p2.y + p3.y) + bi.y, 0.f);
        float v2 = fmaxf((p0.z + p1.z) + (p2.z + p3.z) + bi.z, 0.f);
        float v3 = fmaxf((p0.w + p1.w) + (p2.w + p3.w) + bi.w, 0.f);
        a0 = fmaf(v0, wv.x, a0); a0 = fmaf(v1, wv.y, a0);
        a0 = fmaf(v2, wv.z, a0); a0 = fmaf(v3, wv.w, a0);
        a1 = fmaf(v0, w1[j],     a1); a1 = fmaf(v1, w1[j + 1], a1);
        a1 = fmaf(v2, w1[j + 2], a1); a1 = fmaf(v3, w1[j + 3], a1);
    }
    if (lane == 0) {
        float y0 = y[b * 2], y1 = y[b * 2 + 1];
        a0 += w0[500] * y0 + w0[501] * y1 + b2[0];
        a1 += w1[500] * y0 + w1[501] * y1 + b2[1];
    }
#pragma unroll
    for (int off = 16; off; off >>= 1) {
        a0 += __shfl_xor_sync(0xffffffffu, a0, off);
        a1 += __shfl_xor_sync(0xffffffffu, a1, off);
    }
    if (lane == 0) {
        out[b * 2]     = a0;
        out[b * 2 + 1] = a1;
    }
}

// ---------------- launch ----------------
extern "C" void kernel_launch(void* const* d_in, const int* in_sizes, int n_in,
                              void* d_out, int out_size) {
    const float* x   = (const float*)d_in[0];
    const float* y   = (const float*)d_in[1];
    const float* c1w = (const float*)d_in[2];
    const float* c1b = (const float*)d_in[3];
    const float* c2w = (const float*)d_in[4];
    const float* c2b = (const float*)d_in[5];
    const float* pw  = (const float*)d_in[6];
    const float* pb  = (const float*)d_in[7];
    const float* rw  = (const float*)d_in[8];
    const float* f1w = (const float*)d_in[9];
    const float* f1b = (const float*)d_in[10];
    const float* f2w = (const float*)d_in[11];
    const float* f2b = (const float*)d_in[12];
    float* out = (float*)d_out;

    const int bb_smem  = 93440;
    const int fc1_smem = 56064;
    cudaFuncSetAttribute(backbone_k, cudaFuncAttributeMaxDynamicSharedMemorySize, bb_smem);
    cudaFuncSetAttribute(fc1_mma_k,  cudaFuncAttributeMaxDynamicSharedMemorySize, fc1_smem);

    prep_k<<<512, 256>>>(c2w, pw, f1w);
    backbone_k<<<NB, 288, bb_smem>>>(x, c1w, c1b, c2b, pb, rw);
    dim3 g4(4, 16, 4);
    fc1_mma_k<<<g4, 256, fc1_smem>>>();
    fc2_k<<<NB / 8, 256>>>(y, f1b, f2w, f2b, out);
}